// round 2
// baseline (speedup 1.0000x reference)
#include <cuda_runtime.h>
#include <math.h>

#define NB 2
#define NS 2048
#define NHID 1024
#define NHEADS 16
#define HDIM 64
#define MM (NB * NS)   // 4096

// ---------------- scratch (static device globals; no allocation) ----------
__device__ float g_q[NB * NHEADS * NS * HDIM];   // [b,h,s,d]
__device__ float g_k[NB * NHEADS * NS * HDIM];
__device__ float g_v[NB * NHEADS * NS * HDIM];
__device__ float g_ao[NB * NS * NHID];           // [b,s,h*64+d]
__device__ float g_cos[NS * 32];                 // rope tables [s][d]
__device__ float g_sin[NS * 32];

// ---------------- packed f32x2 helpers ------------------------------------
__device__ __forceinline__ unsigned long long pk2(float a, float b) {
    unsigned long long r;
    asm("mov.b64 %0, {%1,%2};" : "=l"(r) : "f"(a), "f"(b));
    return r;
}
__device__ __forceinline__ void upk2(unsigned long long v, float& a, float& b) {
    asm("mov.b64 {%0,%1}, %2;" : "=f"(a), "=f"(b) : "l"(v));
}
__device__ __forceinline__ void ffma2(unsigned long long& c, unsigned long long a,
                                      unsigned long long b) {
    asm("fma.rn.f32x2 %0, %1, %2, %0;" : "+l"(c) : "l"(a), "l"(b));
}
__device__ __forceinline__ void fmul2(unsigned long long& c, unsigned long long a) {
    asm("mul.rn.f32x2 %0, %0, %1;" : "+l"(c) : "l"(a));
}

// ---------------------------------------------------------------------------
// Core 128x128 tile GEMM body: C[m,n] = sum_k A[m,k]*W[n,k]
// As: k-major [16][128]. Bs: k-major DUPLICATED [16][256] (each value twice),
// so the inner loop needs no packing MOVs: 32 FFMA2 + 6 LDS.128 per k-step.
// acc[i][j] holds rows (2 adjacent m) x col j for this thread.
// ---------------------------------------------------------------------------
struct GemmCore {
    unsigned long long acc[4][8];

    __device__ __forceinline__ void run(const float* __restrict__ Ap,
                                        const float* __restrict__ Wp,
                                        int m0, int n0, int tid) {
        __shared__ float As[16][128];
        __shared__ float Bsd[16][256];

        const int ry = tid >> 4;
        const int tx = tid & 15;
        const int lrow = tid >> 1;
        const int cgb = (tid & 1) * 2;

        const float* ga = Ap + (size_t)(m0 + lrow) * NHID + cgb * 4;
        const float* gw = Wp + (size_t)(n0 + lrow) * NHID + cgb * 4;

#pragma unroll
        for (int i = 0; i < 4; i++)
#pragma unroll
            for (int j = 0; j < 8; j++) acc[i][j] = 0ull;

        float4 pa0 = *(const float4*)(ga);
        float4 pa1 = *(const float4*)(ga + 4);
        float4 pw0 = *(const float4*)(gw);
        float4 pw1 = *(const float4*)(gw + 4);

        const int NKT = NHID / 16;   // 64
        for (int kt = 0; kt < NKT; kt++) {
            As[4 * cgb + 0][lrow] = pa0.x;
            As[4 * cgb + 1][lrow] = pa0.y;
            As[4 * cgb + 2][lrow] = pa0.z;
            As[4 * cgb + 3][lrow] = pa0.w;
            As[4 * cgb + 4][lrow] = pa1.x;
            As[4 * cgb + 5][lrow] = pa1.y;
            As[4 * cgb + 6][lrow] = pa1.z;
            As[4 * cgb + 7][lrow] = pa1.w;
            // duplicated B stores (float2 {v,v})
            *(float2*)&Bsd[4 * cgb + 0][2 * lrow] = make_float2(pw0.x, pw0.x);
            *(float2*)&Bsd[4 * cgb + 1][2 * lrow] = make_float2(pw0.y, pw0.y);
            *(float2*)&Bsd[4 * cgb + 2][2 * lrow] = make_float2(pw0.z, pw0.z);
            *(float2*)&Bsd[4 * cgb + 3][2 * lrow] = make_float2(pw0.w, pw0.w);
            *(float2*)&Bsd[4 * cgb + 4][2 * lrow] = make_float2(pw1.x, pw1.x);
            *(float2*)&Bsd[4 * cgb + 5][2 * lrow] = make_float2(pw1.y, pw1.y);
            *(float2*)&Bsd[4 * cgb + 6][2 * lrow] = make_float2(pw1.z, pw1.z);
            *(float2*)&Bsd[4 * cgb + 7][2 * lrow] = make_float2(pw1.w, pw1.w);
            __syncthreads();

            if (kt + 1 < NKT) {
                const float* ga2 = ga + (kt + 1) * 16;
                const float* gw2 = gw + (kt + 1) * 16;
                pa0 = *(const float4*)(ga2);
                pa1 = *(const float4*)(ga2 + 4);
                pw0 = *(const float4*)(gw2);
                pw1 = *(const float4*)(gw2 + 4);
            }

#pragma unroll
            for (int kk = 0; kk < 16; kk++) {
                ulonglong2 a01 = *(const ulonglong2*)&As[kk][4 * ry];
                ulonglong2 a23 = *(const ulonglong2*)&As[kk][64 + 4 * ry];
                ulonglong2 b01 = *(const ulonglong2*)&Bsd[kk][8 * tx];
                ulonglong2 b23 = *(const ulonglong2*)&Bsd[kk][8 * tx + 4];
                ulonglong2 b45 = *(const ulonglong2*)&Bsd[kk][128 + 8 * tx];
                ulonglong2 b67 = *(const ulonglong2*)&Bsd[kk][128 + 8 * tx + 4];
                unsigned long long av[4] = {a01.x, a01.y, a23.x, a23.y};
                unsigned long long bd[8] = {b01.x, b01.y, b23.x, b23.y,
                                            b45.x, b45.y, b67.x, b67.y};
#pragma unroll
                for (int i = 0; i < 4; i++)
#pragma unroll
                    for (int j = 0; j < 8; j++) ffma2(acc[i][j], av[i], bd[j]);
            }
            __syncthreads();
        }
    }
};

// ---------------------------------------------------------------------------
// QKV projections, merged: blockIdx.z = 0/1/2 -> q/k/v. Stores to [b,h,s,d].
// ---------------------------------------------------------------------------
__global__ __launch_bounds__(256) void gemm_qkv(const float* __restrict__ x,
                                                const float* __restrict__ Wq,
                                                const float* __restrict__ bq,
                                                const float* __restrict__ Wk,
                                                const float* __restrict__ bk,
                                                const float* __restrict__ Wv,
                                                const float* __restrict__ bv) {
    const int z = blockIdx.z;
    const float* W = (z == 0) ? Wq : (z == 1) ? Wk : Wv;
    const float* bias = (z == 0) ? bq : (z == 1) ? bk : bv;
    float* dst = (z == 0) ? g_q : (z == 1) ? g_k : g_v;

    const int tid = threadIdx.x;
    const int m0 = blockIdx.y * 128;
    const int n0 = blockIdx.x * 128;
    const int ry = tid >> 4;
    const int tx = tid & 15;

    GemmCore core;
    core.run(x, W, m0, n0, tid);

#pragma unroll
    for (int i = 0; i < 4; i++) {
        const int rbase = (i < 2) ? (4 * ry + 2 * i) : (64 + 4 * ry + 2 * (i - 2));
#pragma unroll
        for (int j = 0; j < 8; j++) {
            const int col = (j < 4) ? (4 * tx + j) : (64 + 4 * tx + (j - 4));
            float v0, v1;
            upk2(core.acc[i][j], v0, v1);
            const float bv2 = bias[n0 + col];
            v0 += bv2;
            v1 += bv2;
            const int m = m0 + rbase;   // even
            const int n = n0 + col;
            const int b = m >> 11;
            const int s = m & (NS - 1);
            const int h = n >> 6;
            const int d = n & (HDIM - 1);
            const size_t base = (((size_t)(b * NHEADS + h) * NS + s) * HDIM + d);
            dst[base] = v0;
            dst[base + HDIM] = v1;
        }
    }
}

// ---------------------------------------------------------------------------
// Output projection: A = g_ao, C -> out (row-major [m][n]).
// ---------------------------------------------------------------------------
__global__ __launch_bounds__(256) void gemm_proj(const float* __restrict__ Wo,
                                                 const float* __restrict__ bo,
                                                 float* __restrict__ Cout) {
    const int tid = threadIdx.x;
    const int m0 = blockIdx.y * 128;
    const int n0 = blockIdx.x * 128;
    const int ry = tid >> 4;
    const int tx = tid & 15;

    GemmCore core;
    core.run(g_ao, Wo, m0, n0, tid);

#pragma unroll
    for (int i = 0; i < 4; i++) {
        const int rbase = (i < 2) ? (4 * ry + 2 * i) : (64 + 4 * ry + 2 * (i - 2));
#pragma unroll
        for (int j = 0; j < 8; j++) {
            const int col = (j < 4) ? (4 * tx + j) : (64 + 4 * tx + (j - 4));
            float v0, v1;
            upk2(core.acc[i][j], v0, v1);
            const float bv2 = bo[n0 + col];
            v0 += bv2;
            v1 += bv2;
            const int m = m0 + rbase;
            const int n = n0 + col;
            Cout[(size_t)m * NHID + n] = v0;
            Cout[(size_t)(m + 1) * NHID + n] = v1;
        }
    }
}

// ---------------------------------------------------------------------------
// RoPE: (1) precompute 2048x32 cos/sin table in fp64 (65536 threads, cheap),
//       (2) bandwidth-bound apply pass over g_q and g_k.
// ---------------------------------------------------------------------------
__global__ void rope_table() {
    const int t = blockIdx.x * blockDim.x + threadIdx.x;   // 65536
    const int d = t & 31;
    const int s = t >> 5;
    const double inv = exp2(-(double)d * 0.41524101186092029);  // log2(1e4)/32
    double sd, cd;
    sincos((double)s * inv, &sd, &cd);
    g_cos[t] = (float)cd;
    g_sin[t] = (float)sd;
}

__global__ __launch_bounds__(256) void rope_apply() {
    int t = blockIdx.x * blockDim.x + threadIdx.x;
    const int half = NB * NHEADS * NS * 8;   // per-tensor thread count (4 d each)
    float* base = g_q;
    if (t >= half) {
        base = g_k;
        t -= half;
    }
    const int dg = t & 7;           // d-group: 4 pairs
    const int s = (t >> 3) & (NS - 1);
    const int bh = t >> 14;

    const float4 c4 = *(const float4*)&g_cos[s * 32 + dg * 4];
    const float4 s4 = *(const float4*)&g_sin[s * 32 + dg * 4];

    float* p = base + ((size_t)bh * NS + s) * HDIM + dg * 4;
    float4 x1 = *(const float4*)(p);
    float4 x2 = *(const float4*)(p + 32);
    float4 r1, r2;
    r1.x = x1.x * c4.x - x2.x * s4.x;  r2.x = x2.x * c4.x + x1.x * s4.x;
    r1.y = x1.y * c4.y - x2.y * s4.y;  r2.y = x2.y * c4.y + x1.y * s4.y;
    r1.z = x1.z * c4.z - x2.z * s4.z;  r2.z = x2.z * c4.z + x1.z * s4.z;
    r1.w = x1.w * c4.w - x2.w * s4.w;  r2.w = x2.w * c4.w + x1.w * s4.w;
    *(float4*)(p) = r1;
    *(float4*)(p + 32) = r2;
}

// ---------------------------------------------------------------------------
// Flash attention (causal). One CTA per (b, h, 64-row q tile). Unchanged.
// ---------------------------------------------------------------------------
__global__ __launch_bounds__(256) void attn_kernel() {
    extern __shared__ float sm[];
    float* Qd = sm;                  // 64*128
    float* Kt = sm + 64 * 128;       // 64*64
    float* Vs = Kt + 64 * 64;        // 64*64
    float* Pd = Vs + 64 * 64;        // 64*128

    const int qt = (int)(gridDim.x - 1) - (int)blockIdx.x;
    const int h = blockIdx.y;
    const int b = blockIdx.z;
    const int tid = threadIdx.x;
    const int ty = tid >> 4;
    const int tx = tid & 15;

    const float* Qg = g_q + ((size_t)(b * NHEADS + h) * NS + (size_t)qt * 64) * HDIM;
    const float* Kg = g_k + (size_t)(b * NHEADS + h) * NS * HDIM;
    const float* Vg = g_v + (size_t)(b * NHEADS + h) * NS * HDIM;

#pragma unroll
    for (int p = 0; p < 4; p++) {
        const int fid = tid + 256 * p;
        const int row = fid >> 4;
        const int cg = fid & 15;
        float4 v = *(const float4*)(Qg + (size_t)row * HDIM + cg * 4);
        v.x *= 0.125f; v.y *= 0.125f; v.z *= 0.125f; v.w *= 0.125f;
        Qd[(4 * cg + 0) * 128 + 2 * row] = v.x;
        Qd[(4 * cg + 0) * 128 + 2 * row + 1] = v.x;
        Qd[(4 * cg + 1) * 128 + 2 * row] = v.y;
        Qd[(4 * cg + 1) * 128 + 2 * row + 1] = v.y;
        Qd[(4 * cg + 2) * 128 + 2 * row] = v.z;
        Qd[(4 * cg + 2) * 128 + 2 * row + 1] = v.z;
        Qd[(4 * cg + 3) * 128 + 2 * row] = v.w;
        Qd[(4 * cg + 3) * 128 + 2 * row + 1] = v.w;
    }

    const float NEG_INF = __int_as_float(0xff800000);
    float mi[4], li[4];
    unsigned long long o2[4][2];
#pragma unroll
    for (int i = 0; i < 4; i++) {
        mi[i] = NEG_INF;
        li[i] = 0.0f;
        o2[i][0] = 0ull;
        o2[i][1] = 0ull;
    }

    for (int kt = 0; kt <= qt; kt++) {
        __syncthreads();
#pragma unroll
        for (int p = 0; p < 4; p++) {
            const int fid = tid + 256 * p;
            const int row = fid >> 4;
            const int cg = fid & 15;
            const size_t goff = ((size_t)kt * 64 + row) * HDIM + cg * 4;
            float4 kv = *(const float4*)(Kg + goff);
            Kt[(4 * cg + 0) * 64 + row] = kv.x;
            Kt[(4 * cg + 1) * 64 + row] = kv.y;
            Kt[(4 * cg + 2) * 64 + row] = kv.z;
            Kt[(4 * cg + 3) * 64 + row] = kv.w;
            float4 vv = *(const float4*)(Vg + goff);
            *(float4*)&Vs[row * 64 + cg * 4] = vv;
        }
        __syncthreads();

        unsigned long long s2[4][2];
#pragma unroll
        for (int i = 0; i < 4; i++) { s2[i][0] = 0ull; s2[i][1] = 0ull; }

#pragma unroll 8
        for (int d = 0; d < 64; d++) {
            ulonglong2 a01 = *(const ulonglong2*)&Qd[d * 128 + 8 * ty];
            ulonglong2 a23 = *(const ulonglong2*)&Qd[d * 128 + 8 * ty + 4];
            ulonglong2 bb = *(const ulonglong2*)&Kt[d * 64 + 4 * tx];
            unsigned long long av[4] = {a01.x, a01.y, a23.x, a23.y};
#pragma unroll
            for (int i = 0; i < 4; i++) {
                ffma2(s2[i][0], av[i], bb.x);
                ffma2(s2[i][1], av[i], bb.y);
            }
        }

        float sv[4][4];
#pragma unroll
        for (int i = 0; i < 4; i++) {
            upk2(s2[i][0], sv[i][0], sv[i][1]);
            upk2(s2[i][1], sv[i][2], sv[i][3]);
        }

        if (kt == qt) {
#pragma unroll
            for (int i = 0; i < 4; i++) {
                const int qg = 4 * ty + i;
#pragma unroll
                for (int c = 0; c < 4; c++)
                    if (4 * tx + c > qg) sv[i][c] = -1e30f;
            }
        }

#pragma unroll
        for (int i = 0; i < 4; i++) {
            float mx = fmaxf(fmaxf(sv[i][0], sv[i][1]), fmaxf(sv[i][2], sv[i][3]));
#pragma unroll
            for (int o = 1; o < 16; o <<= 1)
                mx = fmaxf(mx, __shfl_xor_sync(0xffffffffu, mx, o));
            const float mnew = fmaxf(mi[i], mx);
            const float corr = __expf(mi[i] - mnew);
            float ps0 = __expf(sv[i][0] - mnew);
            float ps1 = __expf(sv[i][1] - mnew);
            float ps2 = __expf(sv[i][2] - mnew);
            float ps3 = __expf(sv[i][3] - mnew);
            float rs = (ps0 + ps1) + (ps2 + ps3);
#pragma unroll
            for (int o = 1; o < 16; o <<= 1)
                rs += __shfl_xor_sync(0xffffffffu, rs, o);
            li[i] = li[i] * corr + rs;
            mi[i] = mnew;
            const unsigned long long c2 = pk2(corr, corr);
            fmul2(o2[i][0], c2);
            fmul2(o2[i][1], c2);
            const int q2 = 8 * ty + 2 * i;
            Pd[(4 * tx + 0) * 128 + q2] = ps0;
            Pd[(4 * tx + 0) * 128 + q2 + 1] = ps0;
            Pd[(4 * tx + 1) * 128 + q2] = ps1;
            Pd[(4 * tx + 1) * 128 + q2 + 1] = ps1;
            Pd[(4 * tx + 2) * 128 + q2] = ps2;
            Pd[(4 * tx + 2) * 128 + q2 + 1] = ps2;
            Pd[(4 * tx + 3) * 128 + q2] = ps3;
            Pd[(4 * tx + 3) * 128 + q2 + 1] = ps3;
        }
        __syncthreads();

#pragma unroll 8
        for (int k = 0; k < 64; k++) {
            ulonglong2 p01 = *(const ulonglong2*)&Pd[k * 128 + 8 * ty];
            ulonglong2 p23 = *(const ulonglong2*)&Pd[k * 128 + 8 * ty + 4];
            ulonglong2 vv = *(const ulonglong2*)&Vs[k * 64 + 4 * tx];
            unsigned long long av[4] = {p01.x, p01.y, p23.x, p23.y};
#pragma unroll
            for (int i = 0; i < 4; i++) {
                ffma2(o2[i][0], av[i], vv.x);
                ffma2(o2[i][1], av[i], vv.y);
            }
        }
    }

    float* Og = g_ao + ((size_t)b * NS + (size_t)qt * 64) * NHID + h * HDIM;
#pragma unroll
    for (int i = 0; i < 4; i++) {
        const float inv = 1.0f / li[i];
        float v0, v1, v2, v3;
        upk2(o2[i][0], v0, v1);
        upk2(o2[i][1], v2, v3);
        const int row = 4 * ty + i;
        float* op = Og + (size_t)row * NHID + 4 * tx;
        op[0] = v0 * inv;
        op[1] = v1 * inv;
        op[2] = v2 * inv;
        op[3] = v3 * inv;
    }
}

// ---------------------------------------------------------------------------
extern "C" void kernel_launch(void* const* d_in, const int* in_sizes, int n_in,
                              void* d_out, int out_size) {
    const float* x  = (const float*)d_in[0];
    const float* Wq = (const float*)d_in[1];
    const float* bq = (const float*)d_in[2];
    const float* Wk = (const float*)d_in[3];
    const float* bk = (const float*)d_in[4];
    const float* Wv = (const float*)d_in[5];
    const float* bv = (const float*)d_in[6];
    const float* Wo = (const float*)d_in[7];
    const float* bo = (const float*)d_in[8];
    float* out = (float*)d_out;

    cudaFuncSetAttribute(attn_kernel, cudaFuncAttributeMaxDynamicSharedMemorySize,
                         96 * 1024);

    rope_table<<<NS * 32 / 256, 256>>>();

    const dim3 gq(NHID / 128, MM / 128, 3);   // (8, 32, 3) merged QKV
    gemm_qkv<<<gq, 256>>>(x, Wq, bq, Wk, bk, Wv, bv);

    const int rope_threads = 2 * NB * NHEADS * NS * 8;
    rope_apply<<<rope_threads / 256, 256>>>();

    attn_kernel<<<dim3(NS / 64, NHEADS, NB), 256, 96 * 1024>>>();

    gemm_proj<<<dim3(NHID / 128, MM / 128), 256>>>(Wo, bo, out);
}

// round 3
// speedup vs baseline: 1.2570x; 1.2570x over previous
#include <cuda_runtime.h>
#include <math.h>

#define NB 2
#define NS 2048
#define NHID 1024
#define NHEADS 16
#define HDIM 64
#define MM (NB * NS)   // 4096

// ---------------- scratch (static device globals; no allocation) ----------
__device__ float g_q[NB * NHEADS * NS * HDIM];   // [b,h,s,d]
__device__ float g_k[NB * NHEADS * NS * HDIM];
__device__ float g_v[NB * NHEADS * NS * HDIM];
__device__ float g_ao[NB * NS * NHID];           // [b,s,h*64+d]
__device__ float g_cos[NS * 32];                 // rope tables [s][d]
__device__ float g_sin[NS * 32];

// ---------------- packed f32x2 helpers ------------------------------------
__device__ __forceinline__ unsigned long long pk2(float a, float b) {
    unsigned long long r;
    asm("mov.b64 %0, {%1,%2};" : "=l"(r) : "f"(a), "f"(b));
    return r;
}
__device__ __forceinline__ void upk2(unsigned long long v, float& a, float& b) {
    asm("mov.b64 {%0,%1}, %2;" : "=f"(a), "=f"(b) : "l"(v));
}
__device__ __forceinline__ void ffma2(unsigned long long& c, unsigned long long a,
                                      unsigned long long b) {
    asm("fma.rn.f32x2 %0, %1, %2, %0;" : "+l"(c) : "l"(a), "l"(b));
}
__device__ __forceinline__ void fmul2(unsigned long long& c, unsigned long long a) {
    asm("mul.rn.f32x2 %0, %0, %1;" : "+l"(c) : "l"(a));
}

// ---------------------------------------------------------------------------
// Core 128x128 tile GEMM: C[m,n] = sum_k A[m,k]*W[n,k]
// Ad: k-major DUPLICATED [16][256] -- indexed only by ry => warp-broadcast
//     reads, conflict-free at any stride, and FFMA2 A-operand needs no MOVs.
// Bs: k-major compact [16][128]   -- 16B stride per tx => conflict-free;
//     float4 reinterpreted as two packed f32x2 (adjacent n columns pair up).
// Inner loop per kk: 6 LDS.128 + 32 FFMA2 (64 FMA), zero packing MOVs.
// Thread (ry,tx): rows m0+8*ry..+7, cols n0+4*tx..+3 and n0+64+4*tx..+3.
// acc[r][c]: r=row 0..7; c: {cols 4tx+2c,4tx+2c+1} (c<2) / 64+... (c>=2).
// ---------------------------------------------------------------------------
struct GemmCore {
    unsigned long long acc[8][4];

    __device__ __forceinline__ void run(const float* __restrict__ Ap,
                                        const float* __restrict__ Wp,
                                        int m0, int n0, int tid) {
        __shared__ float Ad[16][256];
        __shared__ float Bs[16][128];

        const int ry = tid >> 4;
        const int lrow = tid >> 1;            // 0..127
        const int cgb = (tid & 1) * 2;        // 0 or 2

        const float* ga = Ap + (size_t)(m0 + lrow) * NHID + cgb * 4;
        const float* gw = Wp + (size_t)(n0 + lrow) * NHID + cgb * 4;

#pragma unroll
        for (int r = 0; r < 8; r++)
#pragma unroll
            for (int c = 0; c < 4; c++) acc[r][c] = 0ull;

        float4 pa0 = *(const float4*)(ga);
        float4 pa1 = *(const float4*)(ga + 4);
        float4 pw0 = *(const float4*)(gw);
        float4 pw1 = *(const float4*)(gw + 4);

        const int NKT = NHID / 16;   // 64
        for (int kt = 0; kt < NKT; kt++) {
            // A duplicated stores
            *(float2*)&Ad[4 * cgb + 0][2 * lrow] = make_float2(pa0.x, pa0.x);
            *(float2*)&Ad[4 * cgb + 1][2 * lrow] = make_float2(pa0.y, pa0.y);
            *(float2*)&Ad[4 * cgb + 2][2 * lrow] = make_float2(pa0.z, pa0.z);
            *(float2*)&Ad[4 * cgb + 3][2 * lrow] = make_float2(pa0.w, pa0.w);
            *(float2*)&Ad[4 * cgb + 4][2 * lrow] = make_float2(pa1.x, pa1.x);
            *(float2*)&Ad[4 * cgb + 5][2 * lrow] = make_float2(pa1.y, pa1.y);
            *(float2*)&Ad[4 * cgb + 6][2 * lrow] = make_float2(pa1.z, pa1.z);
            *(float2*)&Ad[4 * cgb + 7][2 * lrow] = make_float2(pa1.w, pa1.w);
            // B compact stores
            Bs[4 * cgb + 0][lrow] = pw0.x;
            Bs[4 * cgb + 1][lrow] = pw0.y;
            Bs[4 * cgb + 2][lrow] = pw0.z;
            Bs[4 * cgb + 3][lrow] = pw0.w;
            Bs[4 * cgb + 4][lrow] = pw1.x;
            Bs[4 * cgb + 5][lrow] = pw1.y;
            Bs[4 * cgb + 6][lrow] = pw1.z;
            Bs[4 * cgb + 7][lrow] = pw1.w;
            __syncthreads();

            if (kt + 1 < NKT) {
                const float* ga2 = ga + (kt + 1) * 16;
                const float* gw2 = gw + (kt + 1) * 16;
                pa0 = *(const float4*)(ga2);
                pa1 = *(const float4*)(ga2 + 4);
                pw0 = *(const float4*)(gw2);
                pw1 = *(const float4*)(gw2 + 4);
            }

            const int tx4 = (tid & 15) * 4;
#pragma unroll
            for (int kk = 0; kk < 16; kk++) {
                ulonglong2 b01 = *(const ulonglong2*)&Bs[kk][tx4];        // cols 4tx..+3
                ulonglong2 b23 = *(const ulonglong2*)&Bs[kk][64 + tx4];   // cols 64+4tx..+3
                unsigned long long bd[4] = {b01.x, b01.y, b23.x, b23.y};
#pragma unroll
                for (int rg = 0; rg < 4; rg++) {
                    ulonglong2 aa = *(const ulonglong2*)&Ad[kk][16 * ry + 4 * rg];
#pragma unroll
                    for (int c = 0; c < 4; c++) {
                        ffma2(acc[2 * rg + 0][c], aa.x, bd[c]);
                        ffma2(acc[2 * rg + 1][c], aa.y, bd[c]);
                    }
                }
            }
            __syncthreads();
        }
    }
};

// ---------------------------------------------------------------------------
// QKV projections, merged: blockIdx.z = 0/1/2 -> q/k/v. Stores to [b,h,s,d].
// ---------------------------------------------------------------------------
__global__ __launch_bounds__(256) void gemm_qkv(const float* __restrict__ x,
                                                const float* __restrict__ Wq,
                                                const float* __restrict__ bq,
                                                const float* __restrict__ Wk,
                                                const float* __restrict__ bk,
                                                const float* __restrict__ Wv,
                                                const float* __restrict__ bv) {
    const int z = blockIdx.z;
    const float* W = (z == 0) ? Wq : (z == 1) ? Wk : Wv;
    const float* bias = (z == 0) ? bq : (z == 1) ? bk : bv;
    float* dst = (z == 0) ? g_q : (z == 1) ? g_k : g_v;

    const int tid = threadIdx.x;
    const int m0 = blockIdx.y * 128;
    const int n0 = blockIdx.x * 128;
    const int ry = tid >> 4;
    const int tx = tid & 15;

    GemmCore core;
    core.run(x, W, m0, n0, tid);

#pragma unroll
    for (int r = 0; r < 8; r++) {
        const int m = m0 + 8 * ry + r;
        const int b = m >> 11;
        const int s = m & (NS - 1);
#pragma unroll
        for (int c = 0; c < 4; c++) {
            const int n = n0 + ((c < 2) ? (4 * tx + 2 * c) : (64 + 4 * tx + 2 * (c - 2)));
            float v0, v1;
            upk2(core.acc[r][c], v0, v1);
            v0 += bias[n];
            v1 += bias[n + 1];
            const int h = n >> 6;
            const int d = n & (HDIM - 1);   // even; d+1 in same head
            const size_t base = (((size_t)(b * NHEADS + h) * NS + s) * HDIM + d);
            *(float2*)&dst[base] = make_float2(v0, v1);
        }
    }
}

// ---------------------------------------------------------------------------
// Output projection: A = g_ao, C -> out (row-major [m][n]).
// ---------------------------------------------------------------------------
__global__ __launch_bounds__(256) void gemm_proj(const float* __restrict__ Wo,
                                                 const float* __restrict__ bo,
                                                 float* __restrict__ Cout) {
    const int tid = threadIdx.x;
    const int m0 = blockIdx.y * 128;
    const int n0 = blockIdx.x * 128;
    const int ry = tid >> 4;
    const int tx = tid & 15;

    GemmCore core;
    core.run(g_ao, Wo, m0, n0, tid);

#pragma unroll
    for (int r = 0; r < 8; r++) {
        const int m = m0 + 8 * ry + r;
#pragma unroll
        for (int c = 0; c < 4; c++) {
            const int n = n0 + ((c < 2) ? (4 * tx + 2 * c) : (64 + 4 * tx + 2 * (c - 2)));
            float v0, v1;
            upk2(core.acc[r][c], v0, v1);
            v0 += bo[n];
            v1 += bo[n + 1];
            *(float2*)&Cout[(size_t)m * NHID + n] = make_float2(v0, v1);
        }
    }
}

// ---------------------------------------------------------------------------
// RoPE: (1) precompute 2048x32 cos/sin table in fp64 (65536 threads, cheap),
//       (2) bandwidth-bound apply pass over g_q and g_k.
// ---------------------------------------------------------------------------
__global__ void rope_table() {
    const int t = blockIdx.x * blockDim.x + threadIdx.x;   // 65536
    const int d = t & 31;
    const int s = t >> 5;
    const double inv = exp2(-(double)d * 0.41524101186092029);  // log2(1e4)/32
    double sd, cd;
    sincos((double)s * inv, &sd, &cd);
    g_cos[t] = (float)cd;
    g_sin[t] = (float)sd;
}

__global__ __launch_bounds__(256) void rope_apply() {
    int t = blockIdx.x * blockDim.x + threadIdx.x;
    const int half = NB * NHEADS * NS * 8;   // per-tensor thread count (4 d each)
    float* base = g_q;
    if (t >= half) {
        base = g_k;
        t -= half;
    }
    const int dg = t & 7;           // d-group: 4 pairs
    const int s = (t >> 3) & (NS - 1);
    const int bh = t >> 14;

    const float4 c4 = *(const float4*)&g_cos[s * 32 + dg * 4];
    const float4 s4 = *(const float4*)&g_sin[s * 32 + dg * 4];

    float* p = base + ((size_t)bh * NS + s) * HDIM + dg * 4;
    float4 x1 = *(const float4*)(p);
    float4 x2 = *(const float4*)(p + 32);
    float4 r1, r2;
    r1.x = x1.x * c4.x - x2.x * s4.x;  r2.x = x2.x * c4.x + x1.x * s4.x;
    r1.y = x1.y * c4.y - x2.y * s4.y;  r2.y = x2.y * c4.y + x1.y * s4.y;
    r1.z = x1.z * c4.z - x2.z * s4.z;  r2.z = x2.z * c4.z + x1.z * s4.z;
    r1.w = x1.w * c4.w - x2.w * s4.w;  r2.w = x2.w * c4.w + x1.w * s4.w;
    *(float4*)(p) = r1;
    *(float4*)(p + 32) = r2;
}

// ---------------------------------------------------------------------------
// Flash attention (causal). One CTA per (b, h, 64-row q tile).
// Already uses duplicated-A(Q,P, broadcast reads) + compact-B(K,V) scheme.
// ---------------------------------------------------------------------------
__global__ __launch_bounds__(256) void attn_kernel() {
    extern __shared__ float sm[];
    float* Qd = sm;                  // 64*128
    float* Kt = sm + 64 * 128;       // 64*64
    float* Vs = Kt + 64 * 64;        // 64*64
    float* Pd = Vs + 64 * 64;        // 64*128

    const int qt = (int)(gridDim.x - 1) - (int)blockIdx.x;
    const int h = blockIdx.y;
    const int b = blockIdx.z;
    const int tid = threadIdx.x;
    const int ty = tid >> 4;
    const int tx = tid & 15;

    const float* Qg = g_q + ((size_t)(b * NHEADS + h) * NS + (size_t)qt * 64) * HDIM;
    const float* Kg = g_k + (size_t)(b * NHEADS + h) * NS * HDIM;
    const float* Vg = g_v + (size_t)(b * NHEADS + h) * NS * HDIM;

#pragma unroll
    for (int p = 0; p < 4; p++) {
        const int fid = tid + 256 * p;
        const int row = fid >> 4;
        const int cg = fid & 15;
        float4 v = *(const float4*)(Qg + (size_t)row * HDIM + cg * 4);
        v.x *= 0.125f; v.y *= 0.125f; v.z *= 0.125f; v.w *= 0.125f;
        Qd[(4 * cg + 0) * 128 + 2 * row] = v.x;
        Qd[(4 * cg + 0) * 128 + 2 * row + 1] = v.x;
        Qd[(4 * cg + 1) * 128 + 2 * row] = v.y;
        Qd[(4 * cg + 1) * 128 + 2 * row + 1] = v.y;
        Qd[(4 * cg + 2) * 128 + 2 * row] = v.z;
        Qd[(4 * cg + 2) * 128 + 2 * row + 1] = v.z;
        Qd[(4 * cg + 3) * 128 + 2 * row] = v.w;
        Qd[(4 * cg + 3) * 128 + 2 * row + 1] = v.w;
    }

    const float NEG_INF = __int_as_float(0xff800000);
    float mi[4], li[4];
    unsigned long long o2[4][2];
#pragma unroll
    for (int i = 0; i < 4; i++) {
        mi[i] = NEG_INF;
        li[i] = 0.0f;
        o2[i][0] = 0ull;
        o2[i][1] = 0ull;
    }

    for (int kt = 0; kt <= qt; kt++) {
        __syncthreads();
#pragma unroll
        for (int p = 0; p < 4; p++) {
            const int fid = tid + 256 * p;
            const int row = fid >> 4;
            const int cg = fid & 15;
            const size_t goff = ((size_t)kt * 64 + row) * HDIM + cg * 4;
            float4 kv = *(const float4*)(Kg + goff);
            Kt[(4 * cg + 0) * 64 + row] = kv.x;
            Kt[(4 * cg + 1) * 64 + row] = kv.y;
            Kt[(4 * cg + 2) * 64 + row] = kv.z;
            Kt[(4 * cg + 3) * 64 + row] = kv.w;
            float4 vv = *(const float4*)(Vg + goff);
            *(float4*)&Vs[row * 64 + cg * 4] = vv;
        }
        __syncthreads();

        unsigned long long s2[4][2];
#pragma unroll
        for (int i = 0; i < 4; i++) { s2[i][0] = 0ull; s2[i][1] = 0ull; }

#pragma unroll 8
        for (int d = 0; d < 64; d++) {
            ulonglong2 a01 = *(const ulonglong2*)&Qd[d * 128 + 8 * ty];
            ulonglong2 a23 = *(const ulonglong2*)&Qd[d * 128 + 8 * ty + 4];
            ulonglong2 bb = *(const ulonglong2*)&Kt[d * 64 + 4 * tx];
            unsigned long long av[4] = {a01.x, a01.y, a23.x, a23.y};
#pragma unroll
            for (int i = 0; i < 4; i++) {
                ffma2(s2[i][0], av[i], bb.x);
                ffma2(s2[i][1], av[i], bb.y);
            }
        }

        float sv[4][4];
#pragma unroll
        for (int i = 0; i < 4; i++) {
            upk2(s2[i][0], sv[i][0], sv[i][1]);
            upk2(s2[i][1], sv[i][2], sv[i][3]);
        }

        if (kt == qt) {
#pragma unroll
            for (int i = 0; i < 4; i++) {
                const int qg = 4 * ty + i;
#pragma unroll
                for (int c = 0; c < 4; c++)
                    if (4 * tx + c > qg) sv[i][c] = -1e30f;
            }
        }

#pragma unroll
        for (int i = 0; i < 4; i++) {
            float mx = fmaxf(fmaxf(sv[i][0], sv[i][1]), fmaxf(sv[i][2], sv[i][3]));
#pragma unroll
            for (int o = 1; o < 16; o <<= 1)
                mx = fmaxf(mx, __shfl_xor_sync(0xffffffffu, mx, o));
            const float mnew = fmaxf(mi[i], mx);
            const float corr = __expf(mi[i] - mnew);
            float ps0 = __expf(sv[i][0] - mnew);
            float ps1 = __expf(sv[i][1] - mnew);
            float ps2 = __expf(sv[i][2] - mnew);
            float ps3 = __expf(sv[i][3] - mnew);
            float rs = (ps0 + ps1) + (ps2 + ps3);
#pragma unroll
            for (int o = 1; o < 16; o <<= 1)
                rs += __shfl_xor_sync(0xffffffffu, rs, o);
            li[i] = li[i] * corr + rs;
            mi[i] = mnew;
            const unsigned long long c2 = pk2(corr, corr);
            fmul2(o2[i][0], c2);
            fmul2(o2[i][1], c2);
            const int q2 = 8 * ty + 2 * i;
            Pd[(4 * tx + 0) * 128 + q2] = ps0;
            Pd[(4 * tx + 0) * 128 + q2 + 1] = ps0;
            Pd[(4 * tx + 1) * 128 + q2] = ps1;
            Pd[(4 * tx + 1) * 128 + q2 + 1] = ps1;
            Pd[(4 * tx + 2) * 128 + q2] = ps2;
            Pd[(4 * tx + 2) * 128 + q2 + 1] = ps2;
            Pd[(4 * tx + 3) * 128 + q2] = ps3;
            Pd[(4 * tx + 3) * 128 + q2 + 1] = ps3;
        }
        __syncthreads();

#pragma unroll 8
        for (int k = 0; k < 64; k++) {
            ulonglong2 p01 = *(const ulonglong2*)&Pd[k * 128 + 8 * ty];
            ulonglong2 p23 = *(const ulonglong2*)&Pd[k * 128 + 8 * ty + 4];
            ulonglong2 vv = *(const ulonglong2*)&Vs[k * 64 + 4 * tx];
            unsigned long long av[4] = {p01.x, p01.y, p23.x, p23.y};
#pragma unroll
            for (int i = 0; i < 4; i++) {
                ffma2(o2[i][0], av[i], vv.x);
                ffma2(o2[i][1], av[i], vv.y);
            }
        }
    }

    float* Og = g_ao + ((size_t)b * NS + (size_t)qt * 64) * NHID + h * HDIM;
#pragma unroll
    for (int i = 0; i < 4; i++) {
        const float inv = 1.0f / li[i];
        float v0, v1, v2, v3;
        upk2(o2[i][0], v0, v1);
        upk2(o2[i][1], v2, v3);
        const int row = 4 * ty + i;
        float* op = Og + (size_t)row * NHID + 4 * tx;
        op[0] = v0 * inv;
        op[1] = v1 * inv;
        op[2] = v2 * inv;
        op[3] = v3 * inv;
    }
}

// ---------------------------------------------------------------------------
extern "C" void kernel_launch(void* const* d_in, const int* in_sizes, int n_in,
                              void* d_out, int out_size) {
    const float* x  = (const float*)d_in[0];
    const float* Wq = (const float*)d_in[1];
    const float* bq = (const float*)d_in[2];
    const float* Wk = (const float*)d_in[3];
    const float* bk = (const float*)d_in[4];
    const float* Wv = (const float*)d_in[5];
    const float* bv = (const float*)d_in[6];
    const float* Wo = (const float*)d_in[7];
    const float* bo = (const float*)d_in[8];
    float* out = (float*)d_out;

    cudaFuncSetAttribute(attn_kernel, cudaFuncAttributeMaxDynamicSharedMemorySize,
                         96 * 1024);

    rope_table<<<NS * 32 / 256, 256>>>();

    const dim3 gq(NHID / 128, MM / 128, 3);   // (8, 32, 3) merged QKV
    gemm_qkv<<<gq, 256>>>(x, Wq, bq, Wk, bk, Wv, bv);

    const int rope_threads = 2 * NB * NHEADS * NS * 8;
    rope_apply<<<rope_threads / 256, 256>>>();

    attn_kernel<<<dim3(NS / 64, NHEADS, NB), 256, 96 * 1024>>>();

    gemm_proj<<<dim3(NHID / 128, MM / 128), 256>>>(Wo, bo, out);
}

// round 6
// speedup vs baseline: 1.6932x; 1.3471x over previous
#include <cuda_runtime.h>
#include <cuda_bf16.h>
#include <stdint.h>
#include <cstdint>
#include <math.h>

#define NB 2
#define NS 2048
#define NHID 1024
#define NHEADS 16
#define HDIM 64
#define MM (NB * NS)   // 4096

// ---------------- scratch (static device globals; no allocation) ----------
__device__ float g_q[NB * NHEADS * NS * HDIM];   // [b,h,s,d]
__device__ float g_k[NB * NHEADS * NS * HDIM];
__device__ float g_v[NB * NHEADS * NS * HDIM];
__device__ float g_ao[NB * NS * NHID];           // [b,s,h*64+d]
__device__ float g_cos[NS * 32];                 // rope tables [s][d]
__device__ float g_sin[NS * 32];

// split-bf16 operands for tensor-core projections
__device__ __nv_bfloat16 g_xh[MM * NHID];
__device__ __nv_bfloat16 g_xl[MM * NHID];
__device__ __nv_bfloat16 g_wh[4 * NHID * NHID];  // Wq,Wk,Wv,Wo
__device__ __nv_bfloat16 g_wl[4 * NHID * NHID];
__device__ __nv_bfloat16 g_aoh[MM * NHID];
__device__ __nv_bfloat16 g_aol[MM * NHID];

// ---------------- packed f32x2 helpers (attention) -------------------------
__device__ __forceinline__ unsigned long long pk2(float a, float b) {
    unsigned long long r;
    asm("mov.b64 %0, {%1,%2};" : "=l"(r) : "f"(a), "f"(b));
    return r;
}
__device__ __forceinline__ void upk2(unsigned long long v, float& a, float& b) {
    asm("mov.b64 {%0,%1}, %2;" : "=f"(a), "=f"(b) : "l"(v));
}
__device__ __forceinline__ void ffma2(unsigned long long& c, unsigned long long a,
                                      unsigned long long b) {
    asm("fma.rn.f32x2 %0, %1, %2, %0;" : "+l"(c) : "l"(a), "l"(b));
}
__device__ __forceinline__ void fmul2(unsigned long long& c, unsigned long long a) {
    asm("mul.rn.f32x2 %0, %0, %1;" : "+l"(c) : "l"(a));
}

// ---------------- mma.sync helpers (base sm_103 ISA; no tcgen05) -----------
__device__ __forceinline__ uint32_t smem_u32(const void* p) {
    uint32_t a;
    asm("{ .reg .u64 t; cvta.to.shared.u64 t, %1; cvt.u32.u64 %0, t; }"
        : "=r"(a) : "l"(p));
    return a;
}
#define LDSM4(r0, r1, r2, r3, addr)                                          \
    asm volatile("ldmatrix.sync.aligned.m8n8.x4.shared.b16 {%0,%1,%2,%3}, [%4];" \
                 : "=r"(r0), "=r"(r1), "=r"(r2), "=r"(r3) : "r"(addr))

__device__ __forceinline__ void mma_bf16(float* d, const uint32_t* a,
                                         const uint32_t* b) {
    asm volatile(
        "mma.sync.aligned.m16n8k16.row.col.f32.bf16.bf16.f32 "
        "{%0,%1,%2,%3}, {%4,%5,%6,%7}, {%8,%9}, {%0,%1,%2,%3};"
        : "+f"(d[0]), "+f"(d[1]), "+f"(d[2]), "+f"(d[3])
        : "r"(a[0]), "r"(a[1]), "r"(a[2]), "r"(a[3]), "r"(b[0]), "r"(b[1]));
}

// ---------------------------------------------------------------------------
// Split fp32 -> bf16 hi/lo. which: 0=x, 1..4=Wq..Wo, 5=g_ao
// ---------------------------------------------------------------------------
__global__ __launch_bounds__(256) void cvt_split(const float* __restrict__ src,
                                                 int which) {
    const int i = 4 * (blockIdx.x * blockDim.x + threadIdx.x);
    const float* s = src;
    __nv_bfloat16 *h, *l;
    if (which == 0)      { h = g_xh;  l = g_xl; }
    else if (which <= 4) { h = g_wh + (size_t)(which - 1) * NHID * NHID;
                           l = g_wl + (size_t)(which - 1) * NHID * NHID; }
    else                 { h = g_aoh; l = g_aol; s = g_ao; }

    float4 v = *(const float4*)(s + i);
    __nv_bfloat16 h0 = __float2bfloat16(v.x);
    __nv_bfloat16 h1 = __float2bfloat16(v.y);
    __nv_bfloat16 h2 = __float2bfloat16(v.z);
    __nv_bfloat16 h3 = __float2bfloat16(v.w);
    __nv_bfloat16 l0 = __float2bfloat16(v.x - __bfloat162float(h0));
    __nv_bfloat16 l1 = __float2bfloat16(v.y - __bfloat162float(h1));
    __nv_bfloat16 l2 = __float2bfloat16(v.z - __bfloat162float(h2));
    __nv_bfloat16 l3 = __float2bfloat16(v.w - __bfloat162float(h3));
    *(__nv_bfloat162*)(h + i)     = __nv_bfloat162(h0, h1);
    *(__nv_bfloat162*)(h + i + 2) = __nv_bfloat162(h2, h3);
    *(__nv_bfloat162*)(l + i)     = __nv_bfloat162(l0, l1);
    *(__nv_bfloat162*)(l + i + 2) = __nv_bfloat162(l2, l3);
}

// ---------------------------------------------------------------------------
// HMMA GEMM: C[m,n] = sum_k A[m,k]*W[n,k] + bias, K=1024.
// Split-bf16 3-pass (hi*hi + hi*lo + lo*hi), fp32 accumulators.
// CTA 128x128, 8 warps in 2x4 grid (64x32 per warp), K-chunks of 64.
// smem: 4 tensors [128][72] bf16 (72-stride => conflict-free ldmatrix).
// ---------------------------------------------------------------------------
#define KC 64
#define NKC (NHID / KC)   // 16
#define ASTR 72
#define TEN_BYTES (128 * ASTR * 2)   // 18432

template <int PROJ>
__global__ __launch_bounds__(256) void gemm_mma(const float* __restrict__ b0p,
                                                const float* __restrict__ b1p,
                                                const float* __restrict__ b2p,
                                                float* __restrict__ Cout) {
    extern __shared__ __nv_bfloat16 sb[];
    __nv_bfloat16* sAh = sb;
    __nv_bfloat16* sAl = sb + 128 * ASTR;
    __nv_bfloat16* sWh = sb + 2 * 128 * ASTR;
    __nv_bfloat16* sWl = sb + 3 * 128 * ASTR;

    const int tid = threadIdx.x;
    const int wid = tid >> 5;
    const int lane = tid & 31;
    const int wr = wid >> 2;        // 0..1 -> m offset 64*wr
    const int wc = wid & 3;         // 0..3 -> n offset 32*wc

    const int n0 = blockIdx.x * 128;
    const int m0 = blockIdx.y * 128;
    const int z = PROJ ? 3 : blockIdx.z;

    const __nv_bfloat16* Ah = PROJ ? g_aoh : g_xh;
    const __nv_bfloat16* Al = PROJ ? g_aol : g_xl;
    const __nv_bfloat16* Wh = g_wh + (size_t)z * NHID * NHID;
    const __nv_bfloat16* Wl = g_wl + (size_t)z * NHID * NHID;
    const float* bias = PROJ ? b0p : (z == 0 ? b0p : (z == 1 ? b1p : b2p));

    float acc[4][4][4];
#pragma unroll
    for (int mt = 0; mt < 4; mt++)
#pragma unroll
        for (int nt = 0; nt < 4; nt++)
#pragma unroll
            for (int e = 0; e < 4; e++) acc[mt][nt][e] = 0.0f;

    // staging indices: 2 threads per row, 32 bf16 (64B) per thread-segment
    const int trow = tid >> 1;
    const int tseg = (tid & 1) * 32;

    const __nv_bfloat16* gAh = Ah + (size_t)(m0 + trow) * NHID + tseg;
    const __nv_bfloat16* gAl = Al + (size_t)(m0 + trow) * NHID + tseg;
    const __nv_bfloat16* gWh = Wh + (size_t)(n0 + trow) * NHID + tseg;
    const __nv_bfloat16* gWl = Wl + (size_t)(n0 + trow) * NHID + tseg;
    __nv_bfloat16* tAh = sAh + trow * ASTR + tseg;
    __nv_bfloat16* tAl = sAl + trow * ASTR + tseg;
    __nv_bfloat16* tWh = sWh + trow * ASTR + tseg;
    __nv_bfloat16* tWl = sWl + trow * ASTR + tseg;

    // ldmatrix lane addressing
    const int a_row = lane & 15;            // m row within 16
    const int a_koff = (lane >> 4) * 8;     // k element offset (0/8)
    const int b_row = (lane & 7) + ((lane >> 4) & 1) * 8;   // n row within 16
    const int b_koff = ((lane >> 3) & 1) * 8;

    const uint32_t uAh = smem_u32(sAh);
    const uint32_t uAl = smem_u32(sAl);
    const uint32_t uWh = smem_u32(sWh);
    const uint32_t uWl = smem_u32(sWl);

    for (int c = 0; c < NKC; c++) {
        __syncthreads();   // previous chunk's compute done before overwrite
        const int kc = c * KC;
#pragma unroll
        for (int j = 0; j < 4; j++) {
            *(uint4*)(tAh + j * 8) = *(const uint4*)(gAh + kc + j * 8);
            *(uint4*)(tAl + j * 8) = *(const uint4*)(gAl + kc + j * 8);
            *(uint4*)(tWh + j * 8) = *(const uint4*)(gWh + kc + j * 8);
            *(uint4*)(tWl + j * 8) = *(const uint4*)(gWl + kc + j * 8);
        }
        __syncthreads();

#pragma unroll
        for (int k16 = 0; k16 < 4; k16++) {
            const int kel = k16 * 16;
            uint32_t ah[4][4], al[4][4], bh[8], bl[8];
#pragma unroll
            for (int mt = 0; mt < 4; mt++) {
                const uint32_t off =
                    2u * ((64 * wr + 16 * mt + a_row) * ASTR + kel + a_koff);
                LDSM4(ah[mt][0], ah[mt][1], ah[mt][2], ah[mt][3], uAh + off);
                LDSM4(al[mt][0], al[mt][1], al[mt][2], al[mt][3], uAl + off);
            }
#pragma unroll
            for (int np = 0; np < 2; np++) {
                const uint32_t off =
                    2u * ((32 * wc + 16 * np + b_row) * ASTR + kel + b_koff);
                LDSM4(bh[4 * np], bh[4 * np + 1], bh[4 * np + 2], bh[4 * np + 3],
                      uWh + off);
                LDSM4(bl[4 * np], bl[4 * np + 1], bl[4 * np + 2], bl[4 * np + 3],
                      uWl + off);
            }
#pragma unroll
            for (int mt = 0; mt < 4; mt++)
#pragma unroll
                for (int nt = 0; nt < 4; nt++) {
                    const uint32_t* bt_h = &bh[4 * (nt >> 1) + 2 * (nt & 1)];
                    const uint32_t* bt_l = &bl[4 * (nt >> 1) + 2 * (nt & 1)];
                    mma_bf16(acc[mt][nt], ah[mt], bt_h);
                    mma_bf16(acc[mt][nt], ah[mt], bt_l);
                    mma_bf16(acc[mt][nt], al[mt], bt_h);
                }
        }
    }

    // ---- epilogue: registers -> global with bias ----
    const int mrow = (lane >> 2);
    const int ncol = (lane & 3) * 2;
#pragma unroll
    for (int mt = 0; mt < 4; mt++) {
#pragma unroll
        for (int half = 0; half < 2; half++) {
            const int m = m0 + 64 * wr + 16 * mt + mrow + 8 * half;
#pragma unroll
            for (int nt = 0; nt < 4; nt++) {
                const int n = n0 + 32 * wc + 8 * nt + ncol;
                float v0 = acc[mt][nt][2 * half] + bias[n];
                float v1 = acc[mt][nt][2 * half + 1] + bias[n + 1];
                if (PROJ) {
                    *(float2*)&Cout[(size_t)m * NHID + n] = make_float2(v0, v1);
                } else {
                    float* dst = (z == 0) ? g_q : (z == 1) ? g_k : g_v;
                    const int bb = m >> 11;
                    const int s = m & (NS - 1);
                    const int h = n >> 6;
                    const int d = n & (HDIM - 1);
                    *(float2*)&dst[(((size_t)(bb * NHEADS + h) * NS + s) * HDIM + d)]
                        = make_float2(v0, v1);
                }
            }
        }
    }
}

// ---------------------------------------------------------------------------
// RoPE: fp64 table + bandwidth apply
// ---------------------------------------------------------------------------
__global__ void rope_table() {
    const int t = blockIdx.x * blockDim.x + threadIdx.x;   // 65536
    const int d = t & 31;
    const int s = t >> 5;
    const double inv = exp2(-(double)d * 0.41524101186092029);
    double sd, cd;
    sincos((double)s * inv, &sd, &cd);
    g_cos[t] = (float)cd;
    g_sin[t] = (float)sd;
}

__global__ __launch_bounds__(256) void rope_apply() {
    int t = blockIdx.x * blockDim.x + threadIdx.x;
    const int half = NB * NHEADS * NS * 8;
    float* base = g_q;
    if (t >= half) {
        base = g_k;
        t -= half;
    }
    const int dg = t & 7;
    const int s = (t >> 3) & (NS - 1);
    const int bh = t >> 14;

    const float4 c4 = *(const float4*)&g_cos[s * 32 + dg * 4];
    const float4 s4 = *(const float4*)&g_sin[s * 32 + dg * 4];

    float* p = base + ((size_t)bh * NS + s) * HDIM + dg * 4;
    float4 x1 = *(const float4*)(p);
    float4 x2 = *(const float4*)(p + 32);
    float4 r1, r2;
    r1.x = x1.x * c4.x - x2.x * s4.x;  r2.x = x2.x * c4.x + x1.x * s4.x;
    r1.y = x1.y * c4.y - x2.y * s4.y;  r2.y = x2.y * c4.y + x1.y * s4.y;
    r1.z = x1.z * c4.z - x2.z * s4.z;  r2.z = x2.z * c4.z + x1.z * s4.z;
    r1.w = x1.w * c4.w - x2.w * s4.w;  r2.w = x2.w * c4.w + x1.w * s4.w;
    *(float4*)(p) = r1;
    *(float4*)(p + 32) = r2;
}

// ---------------------------------------------------------------------------
// Flash attention (causal) — unchanged from round 3.
// ---------------------------------------------------------------------------
__global__ __launch_bounds__(256) void attn_kernel() {
    extern __shared__ float sm[];
    float* Qd = sm;                  // 64*128
    float* Kt = sm + 64 * 128;       // 64*64
    float* Vs = Kt + 64 * 64;        // 64*64
    float* Pd = Vs + 64 * 64;        // 64*128

    const int qt = (int)(gridDim.x - 1) - (int)blockIdx.x;
    const int h = blockIdx.y;
    const int b = blockIdx.z;
    const int tid = threadIdx.x;
    const int ty = tid >> 4;
    const int tx = tid & 15;

    const float* Qg = g_q + ((size_t)(b * NHEADS + h) * NS + (size_t)qt * 64) * HDIM;
    const float* Kg = g_k + (size_t)(b * NHEADS + h) * NS * HDIM;
    const float* Vg = g_v + (size_t)(b * NHEADS + h) * NS * HDIM;

#pragma unroll
    for (int p = 0; p < 4; p++) {
        const int fid = tid + 256 * p;
        const int row = fid >> 4;
        const int cg = fid & 15;
        float4 v = *(const float4*)(Qg + (size_t)row * HDIM + cg * 4);
        v.x *= 0.125f; v.y *= 0.125f; v.z *= 0.125f; v.w *= 0.125f;
        Qd[(4 * cg + 0) * 128 + 2 * row] = v.x;
        Qd[(4 * cg + 0) * 128 + 2 * row + 1] = v.x;
        Qd[(4 * cg + 1) * 128 + 2 * row] = v.y;
        Qd[(4 * cg + 1) * 128 + 2 * row + 1] = v.y;
        Qd[(4 * cg + 2) * 128 + 2 * row] = v.z;
        Qd[(4 * cg + 2) * 128 + 2 * row + 1] = v.z;
        Qd[(4 * cg + 3) * 128 + 2 * row] = v.w;
        Qd[(4 * cg + 3) * 128 + 2 * row + 1] = v.w;
    }

    const float NEG_INF = __int_as_float(0xff800000);
    float mi[4], li[4];
    unsigned long long o2[4][2];
#pragma unroll
    for (int i = 0; i < 4; i++) {
        mi[i] = NEG_INF;
        li[i] = 0.0f;
        o2[i][0] = 0ull;
        o2[i][1] = 0ull;
    }

    for (int kt = 0; kt <= qt; kt++) {
        __syncthreads();
#pragma unroll
        for (int p = 0; p < 4; p++) {
            const int fid = tid + 256 * p;
            const int row = fid >> 4;
            const int cg = fid & 15;
            const size_t goff = ((size_t)kt * 64 + row) * HDIM + cg * 4;
            float4 kv = *(const float4*)(Kg + goff);
            Kt[(4 * cg + 0) * 64 + row] = kv.x;
            Kt[(4 * cg + 1) * 64 + row] = kv.y;
            Kt[(4 * cg + 2) * 64 + row] = kv.z;
            Kt[(4 * cg + 3) * 64 + row] = kv.w;
            float4 vv = *(const float4*)(Vg + goff);
            *(float4*)&Vs[row * 64 + cg * 4] = vv;
        }
        __syncthreads();

        unsigned long long s2[4][2];
#pragma unroll
        for (int i = 0; i < 4; i++) { s2[i][0] = 0ull; s2[i][1] = 0ull; }

#pragma unroll 8
        for (int d = 0; d < 64; d++) {
            ulonglong2 a01 = *(const ulonglong2*)&Qd[d * 128 + 8 * ty];
            ulonglong2 a23 = *(const ulonglong2*)&Qd[d * 128 + 8 * ty + 4];
            ulonglong2 bb = *(const ulonglong2*)&Kt[d * 64 + 4 * tx];
            unsigned long long av[4] = {a01.x, a01.y, a23.x, a23.y};
#pragma unroll
            for (int i = 0; i < 4; i++) {
                ffma2(s2[i][0], av[i], bb.x);
                ffma2(s2[i][1], av[i], bb.y);
            }
        }

        float sv[4][4];
#pragma unroll
        for (int i = 0; i < 4; i++) {
            upk2(s2[i][0], sv[i][0], sv[i][1]);
            upk2(s2[i][1], sv[i][2], sv[i][3]);
        }

        if (kt == qt) {
#pragma unroll
            for (int i = 0; i < 4; i++) {
                const int qg = 4 * ty + i;
#pragma unroll
                for (int c = 0; c < 4; c++)
                    if (4 * tx + c > qg) sv[i][c] = -1e30f;
            }
        }

#pragma unroll
        for (int i = 0; i < 4; i++) {
            float mx = fmaxf(fmaxf(sv[i][0], sv[i][1]), fmaxf(sv[i][2], sv[i][3]));
#pragma unroll
            for (int o = 1; o < 16; o <<= 1)
                mx = fmaxf(mx, __shfl_xor_sync(0xffffffffu, mx, o));
            const float mnew = fmaxf(mi[i], mx);
            const float corr = __expf(mi[i] - mnew);
            float ps0 = __expf(sv[i][0] - mnew);
            float ps1 = __expf(sv[i][1] - mnew);
            float ps2 = __expf(sv[i][2] - mnew);
            float ps3 = __expf(sv[i][3] - mnew);
            float rs = (ps0 + ps1) + (ps2 + ps3);
#pragma unroll
            for (int o = 1; o < 16; o <<= 1)
                rs += __shfl_xor_sync(0xffffffffu, rs, o);
            li[i] = li[i] * corr + rs;
            mi[i] = mnew;
            const unsigned long long c2 = pk2(corr, corr);
            fmul2(o2[i][0], c2);
            fmul2(o2[i][1], c2);
            const int q2 = 8 * ty + 2 * i;
            Pd[(4 * tx + 0) * 128 + q2] = ps0;
            Pd[(4 * tx + 0) * 128 + q2 + 1] = ps0;
            Pd[(4 * tx + 1) * 128 + q2] = ps1;
            Pd[(4 * tx + 1) * 128 + q2 + 1] = ps1;
            Pd[(4 * tx + 2) * 128 + q2] = ps2;
            Pd[(4 * tx + 2) * 128 + q2 + 1] = ps2;
            Pd[(4 * tx + 3) * 128 + q2] = ps3;
            Pd[(4 * tx + 3) * 128 + q2 + 1] = ps3;
        }
        __syncthreads();

#pragma unroll 8
        for (int k = 0; k < 64; k++) {
            ulonglong2 p01 = *(const ulonglong2*)&Pd[k * 128 + 8 * ty];
            ulonglong2 p23 = *(const ulonglong2*)&Pd[k * 128 + 8 * ty + 4];
            ulonglong2 vv = *(const ulonglong2*)&Vs[k * 64 + 4 * tx];
            unsigned long long av[4] = {p01.x, p01.y, p23.x, p23.y};
#pragma unroll
            for (int i = 0; i < 4; i++) {
                ffma2(o2[i][0], av[i], vv.x);
                ffma2(o2[i][1], av[i], vv.y);
            }
        }
    }

    float* Og = g_ao + ((size_t)b * NS + (size_t)qt * 64) * NHID + h * HDIM;
#pragma unroll
    for (int i = 0; i < 4; i++) {
        const float inv = 1.0f / li[i];
        float v0, v1, v2, v3;
        upk2(o2[i][0], v0, v1);
        upk2(o2[i][1], v2, v3);
        const int row = 4 * ty + i;
        float* op = Og + (size_t)row * NHID + 4 * tx;
        op[0] = v0 * inv;
        op[1] = v1 * inv;
        op[2] = v2 * inv;
        op[3] = v3 * inv;
    }
}

// ---------------------------------------------------------------------------
extern "C" void kernel_launch(void* const* d_in, const int* in_sizes, int n_in,
                              void* d_out, int out_size) {
    const float* x  = (const float*)d_in[0];
    const float* Wq = (const float*)d_in[1];
    const float* bq = (const float*)d_in[2];
    const float* Wk = (const float*)d_in[3];
    const float* bk = (const float*)d_in[4];
    const float* Wv = (const float*)d_in[5];
    const float* bv = (const float*)d_in[6];
    const float* Wo = (const float*)d_in[7];
    const float* bo = (const float*)d_in[8];
    float* out = (float*)d_out;

    const int GEMM_SMEM = 4 * TEN_BYTES;   // 73728 B
    cudaFuncSetAttribute(gemm_mma<0>, cudaFuncAttributeMaxDynamicSharedMemorySize,
                         GEMM_SMEM);
    cudaFuncSetAttribute(gemm_mma<1>, cudaFuncAttributeMaxDynamicSharedMemorySize,
                         GEMM_SMEM);
    cudaFuncSetAttribute(attn_kernel, cudaFuncAttributeMaxDynamicSharedMemorySize,
                         96 * 1024);

    rope_table<<<NS * 32 / 256, 256>>>();

    cvt_split<<<MM * NHID / 1024, 256>>>(x, 0);
    cvt_split<<<NHID * NHID / 1024, 256>>>(Wq, 1);
    cvt_split<<<NHID * NHID / 1024, 256>>>(Wk, 2);
    cvt_split<<<NHID * NHID / 1024, 256>>>(Wv, 3);
    cvt_split<<<NHID * NHID / 1024, 256>>>(Wo, 4);

    gemm_mma<0><<<dim3(NHID / 128, MM / 128, 3), 256, GEMM_SMEM>>>(bq, bk, bv,
                                                                   nullptr);

    rope_apply<<<2 * NB * NHEADS * NS * 8 / 256, 256>>>();

    attn_kernel<<<dim3(NS / 64, NHEADS, NB), 256, 96 * 1024>>>();

    cvt_split<<<MM * NHID / 1024, 256>>>(nullptr, 5);
    gemm_mma<1><<<dim3(NHID / 128, MM / 128), 256, GEMM_SMEM>>>(bo, nullptr,
                                                                nullptr, out);
}

// round 7
// speedup vs baseline: 3.8542x; 2.2762x over previous
#include <cuda_runtime.h>
#include <cuda_bf16.h>
#include <stdint.h>
#include <cstdint>
#include <math.h>

#define NB 2
#define NS 2048
#define NHID 1024
#define NHEADS 16
#define HDIM 64
#define MM (NB * NS)   // 4096

// ---------------- scratch (static device globals; no allocation) ----------
__device__ float g_q[NB * NHEADS * NS * HDIM];   // [b,h,s,d]
__device__ float g_k[NB * NHEADS * NS * HDIM];
__device__ float g_v[NB * NHEADS * NS * HDIM];
__device__ float g_ao[NB * NS * NHID];           // [b,s,h*64+d]
__device__ float g_cos[NS * 32];                 // rope tables [s][d]
__device__ float g_sin[NS * 32];

// split-bf16 operands for tensor-core projections
__device__ __nv_bfloat16 g_xh[MM * NHID];
__device__ __nv_bfloat16 g_xl[MM * NHID];
__device__ __nv_bfloat16 g_wh[4 * NHID * NHID];  // Wq,Wk,Wv,Wo
__device__ __nv_bfloat16 g_wl[4 * NHID * NHID];
__device__ __nv_bfloat16 g_aoh[MM * NHID];
__device__ __nv_bfloat16 g_aol[MM * NHID];

// ---------------- mma.sync helpers (base sm_103 ISA) ------------------------
__device__ __forceinline__ uint32_t smem_u32(const void* p) {
    uint32_t a;
    asm("{ .reg .u64 t; cvta.to.shared.u64 t, %1; cvt.u32.u64 %0, t; }"
        : "=r"(a) : "l"(p));
    return a;
}
#define LDSM4(r0, r1, r2, r3, addr)                                          \
    asm volatile("ldmatrix.sync.aligned.m8n8.x4.shared.b16 {%0,%1,%2,%3}, [%4];" \
                 : "=r"(r0), "=r"(r1), "=r"(r2), "=r"(r3) : "r"(addr))
#define LDSM4T(r0, r1, r2, r3, addr)                                         \
    asm volatile(                                                            \
        "ldmatrix.sync.aligned.m8n8.x4.trans.shared.b16 {%0,%1,%2,%3}, [%4];" \
        : "=r"(r0), "=r"(r1), "=r"(r2), "=r"(r3) : "r"(addr))

__device__ __forceinline__ void mma_bf16(float* d, const uint32_t* a,
                                         const uint32_t* b) {
    asm volatile(
        "mma.sync.aligned.m16n8k16.row.col.f32.bf16.bf16.f32 "
        "{%0,%1,%2,%3}, {%4,%5,%6,%7}, {%8,%9}, {%0,%1,%2,%3};"
        : "+f"(d[0]), "+f"(d[1]), "+f"(d[2]), "+f"(d[3])
        : "r"(a[0]), "r"(a[1]), "r"(a[2]), "r"(a[3]), "r"(b[0]), "r"(b[1]));
}

__device__ __forceinline__ uint32_t pkbf(float a, float b) {
    __nv_bfloat162 t = __floats2bfloat162_rn(a, b);
    return *(uint32_t*)&t;
}
// split one float into bf16 hi + bf16 lo
__device__ __forceinline__ void splitf(float v, __nv_bfloat16& h,
                                       __nv_bfloat16& l) {
    h = __float2bfloat16(v);
    l = __float2bfloat16(v - __bfloat162float(h));
}

// ---------------------------------------------------------------------------
// Split fp32 -> bf16 hi/lo. which: 0=x, 1..4=Wq..Wo, 5=g_ao
// ---------------------------------------------------------------------------
__global__ __launch_bounds__(256) void cvt_split(const float* __restrict__ src,
                                                 int which) {
    const int i = 4 * (blockIdx.x * blockDim.x + threadIdx.x);
    const float* s = src;
    __nv_bfloat16 *h, *l;
    if (which == 0)      { h = g_xh;  l = g_xl; }
    else if (which <= 4) { h = g_wh + (size_t)(which - 1) * NHID * NHID;
                           l = g_wl + (size_t)(which - 1) * NHID * NHID; }
    else                 { h = g_aoh; l = g_aol; s = g_ao; }

    float4 v = *(const float4*)(s + i);
    __nv_bfloat16 h0, h1, h2, h3, l0, l1, l2, l3;
    splitf(v.x, h0, l0);
    splitf(v.y, h1, l1);
    splitf(v.z, h2, l2);
    splitf(v.w, h3, l3);
    *(__nv_bfloat162*)(h + i)     = __nv_bfloat162(h0, h1);
    *(__nv_bfloat162*)(h + i + 2) = __nv_bfloat162(h2, h3);
    *(__nv_bfloat162*)(l + i)     = __nv_bfloat162(l0, l1);
    *(__nv_bfloat162*)(l + i + 2) = __nv_bfloat162(l2, l3);
}

// ---------------------------------------------------------------------------
// HMMA GEMM (unchanged from round 6): C = A*W^T + bias, split-bf16 3-pass.
// ---------------------------------------------------------------------------
#define KC 64
#define NKC (NHID / KC)   // 16
#define ASTR 72
#define TEN_BYTES (128 * ASTR * 2)   // 18432

template <int PROJ>
__global__ __launch_bounds__(256) void gemm_mma(const float* __restrict__ b0p,
                                                const float* __restrict__ b1p,
                                                const float* __restrict__ b2p,
                                                float* __restrict__ Cout) {
    extern __shared__ __nv_bfloat16 sb[];
    __nv_bfloat16* sAh = sb;
    __nv_bfloat16* sAl = sb + 128 * ASTR;
    __nv_bfloat16* sWh = sb + 2 * 128 * ASTR;
    __nv_bfloat16* sWl = sb + 3 * 128 * ASTR;

    const int tid = threadIdx.x;
    const int wid = tid >> 5;
    const int lane = tid & 31;
    const int wr = wid >> 2;
    const int wc = wid & 3;

    const int n0 = blockIdx.x * 128;
    const int m0 = blockIdx.y * 128;
    const int z = PROJ ? 3 : blockIdx.z;

    const __nv_bfloat16* Ah = PROJ ? g_aoh : g_xh;
    const __nv_bfloat16* Al = PROJ ? g_aol : g_xl;
    const __nv_bfloat16* Wh = g_wh + (size_t)z * NHID * NHID;
    const __nv_bfloat16* Wl = g_wl + (size_t)z * NHID * NHID;
    const float* bias = PROJ ? b0p : (z == 0 ? b0p : (z == 1 ? b1p : b2p));

    float acc[4][4][4];
#pragma unroll
    for (int mt = 0; mt < 4; mt++)
#pragma unroll
        for (int nt = 0; nt < 4; nt++)
#pragma unroll
            for (int e = 0; e < 4; e++) acc[mt][nt][e] = 0.0f;

    const int trow = tid >> 1;
    const int tseg = (tid & 1) * 32;

    const __nv_bfloat16* gAh = Ah + (size_t)(m0 + trow) * NHID + tseg;
    const __nv_bfloat16* gAl = Al + (size_t)(m0 + trow) * NHID + tseg;
    const __nv_bfloat16* gWh = Wh + (size_t)(n0 + trow) * NHID + tseg;
    const __nv_bfloat16* gWl = Wl + (size_t)(n0 + trow) * NHID + tseg;
    __nv_bfloat16* tAh = sAh + trow * ASTR + tseg;
    __nv_bfloat16* tAl = sAl + trow * ASTR + tseg;
    __nv_bfloat16* tWh = sWh + trow * ASTR + tseg;
    __nv_bfloat16* tWl = sWl + trow * ASTR + tseg;

    const int a_row = lane & 15;
    const int a_koff = (lane >> 4) * 8;
    const int b_row = (lane & 7) + ((lane >> 4) & 1) * 8;
    const int b_koff = ((lane >> 3) & 1) * 8;

    const uint32_t uAh = smem_u32(sAh);
    const uint32_t uAl = smem_u32(sAl);
    const uint32_t uWh = smem_u32(sWh);
    const uint32_t uWl = smem_u32(sWl);

    for (int c = 0; c < NKC; c++) {
        __syncthreads();
        const int kc = c * KC;
#pragma unroll
        for (int j = 0; j < 4; j++) {
            *(uint4*)(tAh + j * 8) = *(const uint4*)(gAh + kc + j * 8);
            *(uint4*)(tAl + j * 8) = *(const uint4*)(gAl + kc + j * 8);
            *(uint4*)(tWh + j * 8) = *(const uint4*)(gWh + kc + j * 8);
            *(uint4*)(tWl + j * 8) = *(const uint4*)(gWl + kc + j * 8);
        }
        __syncthreads();

#pragma unroll
        for (int k16 = 0; k16 < 4; k16++) {
            const int kel = k16 * 16;
            uint32_t ah[4][4], al[4][4], bh[8], bl[8];
#pragma unroll
            for (int mt = 0; mt < 4; mt++) {
                const uint32_t off =
                    2u * ((64 * wr + 16 * mt + a_row) * ASTR + kel + a_koff);
                LDSM4(ah[mt][0], ah[mt][1], ah[mt][2], ah[mt][3], uAh + off);
                LDSM4(al[mt][0], al[mt][1], al[mt][2], al[mt][3], uAl + off);
            }
#pragma unroll
            for (int np = 0; np < 2; np++) {
                const uint32_t off =
                    2u * ((32 * wc + 16 * np + b_row) * ASTR + kel + b_koff);
                LDSM4(bh[4 * np], bh[4 * np + 1], bh[4 * np + 2], bh[4 * np + 3],
                      uWh + off);
                LDSM4(bl[4 * np], bl[4 * np + 1], bl[4 * np + 2], bl[4 * np + 3],
                      uWl + off);
            }
#pragma unroll
            for (int mt = 0; mt < 4; mt++)
#pragma unroll
                for (int nt = 0; nt < 4; nt++) {
                    const uint32_t* bt_h = &bh[4 * (nt >> 1) + 2 * (nt & 1)];
                    const uint32_t* bt_l = &bl[4 * (nt >> 1) + 2 * (nt & 1)];
                    mma_bf16(acc[mt][nt], ah[mt], bt_h);
                    mma_bf16(acc[mt][nt], ah[mt], bt_l);
                    mma_bf16(acc[mt][nt], al[mt], bt_h);
                }
        }
    }

    const int mrow = (lane >> 2);
    const int ncol = (lane & 3) * 2;
#pragma unroll
    for (int mt = 0; mt < 4; mt++) {
#pragma unroll
        for (int half = 0; half < 2; half++) {
            const int m = m0 + 64 * wr + 16 * mt + mrow + 8 * half;
#pragma unroll
            for (int nt = 0; nt < 4; nt++) {
                const int n = n0 + 32 * wc + 8 * nt + ncol;
                float v0 = acc[mt][nt][2 * half] + bias[n];
                float v1 = acc[mt][nt][2 * half + 1] + bias[n + 1];
                if (PROJ) {
                    *(float2*)&Cout[(size_t)m * NHID + n] = make_float2(v0, v1);
                } else {
                    float* dst = (z == 0) ? g_q : (z == 1) ? g_k : g_v;
                    const int bb = m >> 11;
                    const int s = m & (NS - 1);
                    const int h = n >> 6;
                    const int d = n & (HDIM - 1);
                    *(float2*)&dst[(((size_t)(bb * NHEADS + h) * NS + s) * HDIM + d)]
                        = make_float2(v0, v1);
                }
            }
        }
    }
}

// ---------------------------------------------------------------------------
// RoPE: fp64 table + bandwidth apply (unchanged)
// ---------------------------------------------------------------------------
__global__ void rope_table() {
    const int t = blockIdx.x * blockDim.x + threadIdx.x;   // 65536
    const int d = t & 31;
    const int s = t >> 5;
    const double inv = exp2(-(double)d * 0.41524101186092029);
    double sd, cd;
    sincos((double)s * inv, &sd, &cd);
    g_cos[t] = (float)cd;
    g_sin[t] = (float)sd;
}

__global__ __launch_bounds__(256) void rope_apply() {
    int t = blockIdx.x * blockDim.x + threadIdx.x;
    const int half = NB * NHEADS * NS * 8;
    float* base = g_q;
    if (t >= half) {
        base = g_k;
        t -= half;
    }
    const int dg = t & 7;
    const int s = (t >> 3) & (NS - 1);
    const int bh = t >> 14;

    const float4 c4 = *(const float4*)&g_cos[s * 32 + dg * 4];
    const float4 s4 = *(const float4*)&g_sin[s * 32 + dg * 4];

    float* p = base + ((size_t)bh * NS + s) * HDIM + dg * 4;
    float4 x1 = *(const float4*)(p);
    float4 x2 = *(const float4*)(p + 32);
    float4 r1, r2;
    r1.x = x1.x * c4.x - x2.x * s4.x;  r2.x = x2.x * c4.x + x1.x * s4.x;
    r1.y = x1.y * c4.y - x2.y * s4.y;  r2.y = x2.y * c4.y + x1.y * s4.y;
    r1.z = x1.z * c4.z - x2.z * s4.z;  r2.z = x2.z * c4.z + x1.z * s4.z;
    r1.w = x1.w * c4.w - x2.w * s4.w;  r2.w = x2.w * c4.w + x1.w * s4.w;
    *(float4*)(p) = r1;
    *(float4*)(p + 32) = r2;
}

// ---------------------------------------------------------------------------
// Flash attention via HMMA (FA2-style). CTA = (b, h, 128-row q tile).
// 8 warps x 16 q-rows. K/V tiles of 64. Split-bf16 3-pass for S and PV.
// Q pre-scaled + split once into smem; P reused from S accumulators
// (register-level fragment identity), V via ldmatrix.trans.
// ---------------------------------------------------------------------------
#define BQ 128
#define BK 64
#define KSTR 72

__global__ __launch_bounds__(256) void attn_mma() {
    extern __shared__ __nv_bfloat16 sa_[];
    __nv_bfloat16* sQh = sa_;                       // 128*72
    __nv_bfloat16* sQl = sa_ + 128 * KSTR;
    __nv_bfloat16* sKh = sa_ + 2 * 128 * KSTR;      // 64*72 each below
    __nv_bfloat16* sKl = sKh + 64 * KSTR;
    __nv_bfloat16* sVh = sKl + 64 * KSTR;
    __nv_bfloat16* sVl = sVh + 64 * KSTR;

    const int qt = (int)(gridDim.x - 1) - (int)blockIdx.x;   // big tiles first
    const int h = blockIdx.y;
    const int b = blockIdx.z;
    const int tid = threadIdx.x;
    const int wid = tid >> 5;
    const int lane = tid & 31;

    const float* Qg = g_q + ((size_t)(b * NHEADS + h) * NS + (size_t)qt * BQ) * HDIM;
    const float* Kg = g_k + (size_t)(b * NHEADS + h) * NS * HDIM;
    const float* Vg = g_v + (size_t)(b * NHEADS + h) * NS * HDIM;

    // ---- load Q (scale 0.125, split) ----
    {
        const int row = tid >> 1;
        const int c0 = (tid & 1) * 32;
        const float* src = Qg + (size_t)row * HDIM + c0;
        __nv_bfloat16* dh = sQh + row * KSTR + c0;
        __nv_bfloat16* dl = sQl + row * KSTR + c0;
#pragma unroll
        for (int j = 0; j < 8; j++) {
            float4 v = *(const float4*)(src + 4 * j);
            v.x *= 0.125f; v.y *= 0.125f; v.z *= 0.125f; v.w *= 0.125f;
            __nv_bfloat16 h0, h1, h2, h3, l0, l1, l2, l3;
            splitf(v.x, h0, l0);
            splitf(v.y, h1, l1);
            splitf(v.z, h2, l2);
            splitf(v.w, h3, l3);
            *(__nv_bfloat162*)(dh + 4 * j)     = __nv_bfloat162(h0, h1);
            *(__nv_bfloat162*)(dh + 4 * j + 2) = __nv_bfloat162(h2, h3);
            *(__nv_bfloat162*)(dl + 4 * j)     = __nv_bfloat162(l0, l1);
            *(__nv_bfloat162*)(dl + 4 * j + 2) = __nv_bfloat162(l2, l3);
        }
    }

    const int a_row = lane & 15;
    const int a_koff = (lane >> 4) * 8;
    const int b_row = (lane & 7) + ((lane >> 4) & 1) * 8;
    const int b_koff = ((lane >> 3) & 1) * 8;
    const int v_kr = (lane & 7) + 8 * ((lane >> 3) & 1);   // trans ldmatrix row
    const int v_nc = 8 * (lane >> 4);                      // trans ldmatrix col

    const uint32_t uQh = smem_u32(sQh);
    const uint32_t uQl = smem_u32(sQl);
    const uint32_t uKh = smem_u32(sKh);
    const uint32_t uKl = smem_u32(sKl);
    const uint32_t uVh = smem_u32(sVh);
    const uint32_t uVl = smem_u32(sVl);

    float o[8][4];
#pragma unroll
    for (int j = 0; j < 8; j++)
#pragma unroll
        for (int e = 0; e < 4; e++) o[j][e] = 0.0f;
    float mi0 = -1e30f, mi1 = -1e30f, li0 = 0.0f, li1 = 0.0f;

    const int qrow0 = qt * BQ + wid * 16 + (lane >> 2);   // global q row (c0,c1)
    const int qrow1 = qrow0 + 8;                          // (c2,c3)
    const int kcbase = 2 * (lane & 3);

    const int ktmax = 2 * qt + 1;
    for (int kt = 0; kt <= ktmax; kt++) {
        __syncthreads();   // prior iteration done reading sK/sV
        // ---- load + split K, V tiles (64 x 64) ----
        {
            const int row = tid >> 2;
            const int c0 = (tid & 3) * 16;
            const float* ks = Kg + ((size_t)kt * BK + row) * HDIM + c0;
            const float* vs = Vg + ((size_t)kt * BK + row) * HDIM + c0;
            __nv_bfloat16* kh = sKh + row * KSTR + c0;
            __nv_bfloat16* kl = sKl + row * KSTR + c0;
            __nv_bfloat16* vh = sVh + row * KSTR + c0;
            __nv_bfloat16* vl = sVl + row * KSTR + c0;
#pragma unroll
            for (int j = 0; j < 4; j++) {
                float4 kv = *(const float4*)(ks + 4 * j);
                __nv_bfloat16 h0, h1, h2, h3, l0, l1, l2, l3;
                splitf(kv.x, h0, l0);
                splitf(kv.y, h1, l1);
                splitf(kv.z, h2, l2);
                splitf(kv.w, h3, l3);
                *(__nv_bfloat162*)(kh + 4 * j)     = __nv_bfloat162(h0, h1);
                *(__nv_bfloat162*)(kh + 4 * j + 2) = __nv_bfloat162(h2, h3);
                *(__nv_bfloat162*)(kl + 4 * j)     = __nv_bfloat162(l0, l1);
                *(__nv_bfloat162*)(kl + 4 * j + 2) = __nv_bfloat162(l2, l3);
                float4 vv = *(const float4*)(vs + 4 * j);
                splitf(vv.x, h0, l0);
                splitf(vv.y, h1, l1);
                splitf(vv.z, h2, l2);
                splitf(vv.w, h3, l3);
                *(__nv_bfloat162*)(vh + 4 * j)     = __nv_bfloat162(h0, h1);
                *(__nv_bfloat162*)(vh + 4 * j + 2) = __nv_bfloat162(h2, h3);
                *(__nv_bfloat162*)(vl + 4 * j)     = __nv_bfloat162(l0, l1);
                *(__nv_bfloat162*)(vl + 4 * j + 2) = __nv_bfloat162(l2, l3);
            }
        }
        __syncthreads();

        // ---- S = Q @ K^T (16 x 64 per warp), 3-pass split ----
        float s[8][4];
#pragma unroll
        for (int j = 0; j < 8; j++)
#pragma unroll
            for (int e = 0; e < 4; e++) s[j][e] = 0.0f;

#pragma unroll
        for (int k16 = 0; k16 < 4; k16++) {
            const int kel = 16 * k16;
            uint32_t qh[4], ql[4], kh[4][4], kl[4][4];
            {
                const uint32_t off =
                    2u * ((wid * 16 + a_row) * KSTR + kel + a_koff);
                LDSM4(qh[0], qh[1], qh[2], qh[3], uQh + off);
                LDSM4(ql[0], ql[1], ql[2], ql[3], uQl + off);
            }
#pragma unroll
            for (int ng = 0; ng < 4; ng++) {
                const uint32_t off =
                    2u * ((16 * ng + b_row) * KSTR + kel + b_koff);
                LDSM4(kh[ng][0], kh[ng][1], kh[ng][2], kh[ng][3], uKh + off);
                LDSM4(kl[ng][0], kl[ng][1], kl[ng][2], kl[ng][3], uKl + off);
            }
#pragma unroll
            for (int j = 0; j < 8; j++) {
                const uint32_t* bh = &kh[j >> 1][2 * (j & 1)];
                const uint32_t* bl = &kl[j >> 1][2 * (j & 1)];
                mma_bf16(s[j], qh, bh);
                mma_bf16(s[j], qh, bl);
                mma_bf16(s[j], ql, bh);
            }
        }

        // ---- causal mask (diagonal-overlap tiles only) ----
        if (kt * BK + BK - 1 > qrow0) {
#pragma unroll
            for (int j = 0; j < 8; j++) {
                const int kc = kt * BK + 8 * j + kcbase;
                if (kc > qrow0) s[j][0] = -1e30f;
                if (kc + 1 > qrow0) s[j][1] = -1e30f;
            }
        }
        if (kt * BK + BK - 1 > qrow1) {
#pragma unroll
            for (int j = 0; j < 8; j++) {
                const int kc = kt * BK + 8 * j + kcbase;
                if (kc > qrow1) s[j][2] = -1e30f;
                if (kc + 1 > qrow1) s[j][3] = -1e30f;
            }
        }

        // ---- online softmax ----
        float mx0 = s[0][0], mx1 = s[0][2];
#pragma unroll
        for (int j = 0; j < 8; j++) {
            mx0 = fmaxf(mx0, fmaxf(s[j][0], s[j][1]));
            mx1 = fmaxf(mx1, fmaxf(s[j][2], s[j][3]));
        }
        mx0 = fmaxf(mx0, __shfl_xor_sync(0xffffffffu, mx0, 1));
        mx0 = fmaxf(mx0, __shfl_xor_sync(0xffffffffu, mx0, 2));
        mx1 = fmaxf(mx1, __shfl_xor_sync(0xffffffffu, mx1, 1));
        mx1 = fmaxf(mx1, __shfl_xor_sync(0xffffffffu, mx1, 2));

        const float mn0 = fmaxf(mi0, mx0);
        const float mn1 = fmaxf(mi1, mx1);
        const float cr0 = __expf(mi0 - mn0);
        const float cr1 = __expf(mi1 - mn1);

        float rs0 = 0.0f, rs1 = 0.0f;
#pragma unroll
        for (int j = 0; j < 8; j++) {
            s[j][0] = __expf(s[j][0] - mn0);
            s[j][1] = __expf(s[j][1] - mn0);
            s[j][2] = __expf(s[j][2] - mn1);
            s[j][3] = __expf(s[j][3] - mn1);
            rs0 += s[j][0] + s[j][1];
            rs1 += s[j][2] + s[j][3];
        }
        rs0 += __shfl_xor_sync(0xffffffffu, rs0, 1);
        rs0 += __shfl_xor_sync(0xffffffffu, rs0, 2);
        rs1 += __shfl_xor_sync(0xffffffffu, rs1, 1);
        rs1 += __shfl_xor_sync(0xffffffffu, rs1, 2);
        li0 = li0 * cr0 + rs0;
        li1 = li1 * cr1 + rs1;
        mi0 = mn0;
        mi1 = mn1;

#pragma unroll
        for (int j = 0; j < 8; j++) {
            o[j][0] *= cr0;
            o[j][1] *= cr0;
            o[j][2] *= cr1;
            o[j][3] *= cr1;
        }

        // ---- O += P @ V (P from registers, V via trans ldmatrix) ----
#pragma unroll
        for (int t = 0; t < 4; t++) {
            // P fragments for k16 chunk t (= n8 tiles 2t, 2t+1)
            uint32_t ph[4], pl[4];
            {
                const float* p0 = s[2 * t];
                const float* p1 = s[2 * t + 1];
                __nv_bfloat16 hh, ll;
                float r[8];
                __nv_bfloat16 hb[8];
#pragma unroll
                for (int e = 0; e < 4; e++) {
                    splitf(p0[e], hh, ll);
                    hb[e] = hh;
                    r[e] = __bfloat162float(ll);
                    splitf(p1[e], hh, ll);
                    hb[4 + e] = hh;
                    r[4 + e] = __bfloat162float(ll);
                }
                ph[0] = *(uint32_t*)&hb[0];           // (hb0,hb1) packed? no
                // pack explicitly to keep ordering correct:
                ph[0] = pkbf(__bfloat162float(hb[0]), __bfloat162float(hb[1]));
                ph[1] = pkbf(__bfloat162float(hb[2]), __bfloat162float(hb[3]));
                ph[2] = pkbf(__bfloat162float(hb[4]), __bfloat162float(hb[5]));
                ph[3] = pkbf(__bfloat162float(hb[6]), __bfloat162float(hb[7]));
                pl[0] = pkbf(r[0], r[1]);
                pl[1] = pkbf(r[2], r[3]);
                pl[2] = pkbf(r[4], r[5]);
                pl[3] = pkbf(r[6], r[7]);
            }
            const int kel = 16 * t;
            uint32_t vh[4][4], vl[4][4];
#pragma unroll
            for (int ng = 0; ng < 4; ng++) {
                const uint32_t off =
                    2u * ((kel + v_kr) * KSTR + 16 * ng + v_nc);
                LDSM4T(vh[ng][0], vh[ng][1], vh[ng][2], vh[ng][3], uVh + off);
                LDSM4T(vl[ng][0], vl[ng][1], vl[ng][2], vl[ng][3], uVl + off);
            }
#pragma unroll
            for (int j = 0; j < 8; j++) {
                const uint32_t* bvh = &vh[j >> 1][2 * (j & 1)];
                const uint32_t* bvl = &vl[j >> 1][2 * (j & 1)];
                mma_bf16(o[j], ph, bvh);
                mma_bf16(o[j], ph, bvl);
                mma_bf16(o[j], pl, bvh);
            }
        }
    }

    // ---- normalize + store to g_ao [b, s, h*64+d] ----
    const float inv0 = 1.0f / li0;
    const float inv1 = 1.0f / li1;
    float* O0 = g_ao + ((size_t)b * NS + qrow0) * NHID + h * HDIM;
    float* O1 = g_ao + ((size_t)b * NS + qrow1) * NHID + h * HDIM;
#pragma unroll
    for (int j = 0; j < 8; j++) {
        const int d = 8 * j + kcbase;
        *(float2*)(O0 + d) = make_float2(o[j][0] * inv0, o[j][1] * inv0);
        *(float2*)(O1 + d) = make_float2(o[j][2] * inv1, o[j][3] * inv1);
    }
}

// ---------------------------------------------------------------------------
extern "C" void kernel_launch(void* const* d_in, const int* in_sizes, int n_in,
                              void* d_out, int out_size) {
    const float* x  = (const float*)d_in[0];
    const float* Wq = (const float*)d_in[1];
    const float* bq = (const float*)d_in[2];
    const float* Wk = (const float*)d_in[3];
    const float* bk = (const float*)d_in[4];
    const float* Wv = (const float*)d_in[5];
    const float* bv = (const float*)d_in[6];
    const float* Wo = (const float*)d_in[7];
    const float* bo = (const float*)d_in[8];
    float* out = (float*)d_out;

    const int GEMM_SMEM = 4 * TEN_BYTES;                    // 73728 B
    const int ATTN_SMEM = (2 * 128 + 4 * 64) * KSTR * 2;    // 73728 B
    cudaFuncSetAttribute(gemm_mma<0>, cudaFuncAttributeMaxDynamicSharedMemorySize,
                         GEMM_SMEM);
    cudaFuncSetAttribute(gemm_mma<1>, cudaFuncAttributeMaxDynamicSharedMemorySize,
                         GEMM_SMEM);
    cudaFuncSetAttribute(attn_mma, cudaFuncAttributeMaxDynamicSharedMemorySize,
                         ATTN_SMEM);

    rope_table<<<NS * 32 / 256, 256>>>();

    cvt_split<<<MM * NHID / 1024, 256>>>(x, 0);
    cvt_split<<<NHID * NHID / 1024, 256>>>(Wq, 1);
    cvt_split<<<NHID * NHID / 1024, 256>>>(Wk, 2);
    cvt_split<<<NHID * NHID / 1024, 256>>>(Wv, 3);
    cvt_split<<<NHID * NHID / 1024, 256>>>(Wo, 4);

    gemm_mma<0><<<dim3(NHID / 128, MM / 128, 3), 256, GEMM_SMEM>>>(bq, bk, bv,
                                                                   nullptr);

    rope_apply<<<2 * NB * NHEADS * NS * 8 / 256, 256>>>();

    attn_mma<<<dim3(NS / BQ, NHEADS, NB), 256, ATTN_SMEM>>>();

    cvt_split<<<MM * NHID / 1024, 256>>>(nullptr, 5);
    gemm_mma<1><<<dim3(NHID / 128, MM / 128), 256, GEMM_SMEM>>>(bo, nullptr,
                                                                nullptr, out);
}

// round 8
// speedup vs baseline: 4.3605x; 1.1314x over previous
#include <cuda_runtime.h>
#include <cuda_bf16.h>
#include <stdint.h>
#include <cstdint>
#include <math.h>

#define NB 2
#define NS 2048
#define NHID 1024
#define NHEADS 16
#define HDIM 64
#define MM (NB * NS)   // 4096

// ---------------- scratch (static device globals; no allocation) ----------
__device__ float g_q[NB * NHEADS * NS * HDIM];   // [b,h,s,d] fp32 (pre-rope)
__device__ float g_k[NB * NHEADS * NS * HDIM];
__device__ float g_cos[NS * 32];                 // rope tables [s][d]
__device__ float g_sin[NS * 32];

// split-bf16 operands
__device__ __nv_bfloat16 g_xh[MM * NHID];
__device__ __nv_bfloat16 g_xl[MM * NHID];
__device__ __nv_bfloat16 g_wh[4 * NHID * NHID];  // Wq,Wk,Wv,Wo
__device__ __nv_bfloat16 g_wl[4 * NHID * NHID];
__device__ __nv_bfloat16 g_aoh[MM * NHID];       // attention output, split
__device__ __nv_bfloat16 g_aol[MM * NHID];
// rope-rotated, split q/k (q pre-scaled by 0.125) + split v, [b,h,s,d]
__device__ __nv_bfloat16 g_qh[NB * NHEADS * NS * HDIM];
__device__ __nv_bfloat16 g_ql[NB * NHEADS * NS * HDIM];
__device__ __nv_bfloat16 g_kh[NB * NHEADS * NS * HDIM];
__device__ __nv_bfloat16 g_kl[NB * NHEADS * NS * HDIM];
__device__ __nv_bfloat16 g_vh[NB * NHEADS * NS * HDIM];
__device__ __nv_bfloat16 g_vl[NB * NHEADS * NS * HDIM];

// ---------------- mma.sync helpers (base sm_103 ISA) ------------------------
__device__ __forceinline__ uint32_t smem_u32(const void* p) {
    uint32_t a;
    asm("{ .reg .u64 t; cvta.to.shared.u64 t, %1; cvt.u32.u64 %0, t; }"
        : "=r"(a) : "l"(p));
    return a;
}
#define LDSM4(r0, r1, r2, r3, addr)                                          \
    asm volatile("ldmatrix.sync.aligned.m8n8.x4.shared.b16 {%0,%1,%2,%3}, [%4];" \
                 : "=r"(r0), "=r"(r1), "=r"(r2), "=r"(r3) : "r"(addr))
#define LDSM4T(r0, r1, r2, r3, addr)                                         \
    asm volatile(                                                            \
        "ldmatrix.sync.aligned.m8n8.x4.trans.shared.b16 {%0,%1,%2,%3}, [%4];" \
        : "=r"(r0), "=r"(r1), "=r"(r2), "=r"(r3) : "r"(addr))

__device__ __forceinline__ void mma_bf16(float* d, const uint32_t* a,
                                         const uint32_t* b) {
    asm volatile(
        "mma.sync.aligned.m16n8k16.row.col.f32.bf16.bf16.f32 "
        "{%0,%1,%2,%3}, {%4,%5,%6,%7}, {%8,%9}, {%0,%1,%2,%3};"
        : "+f"(d[0]), "+f"(d[1]), "+f"(d[2]), "+f"(d[3])
        : "r"(a[0]), "r"(a[1]), "r"(a[2]), "r"(a[3]), "r"(b[0]), "r"(b[1]));
}

__device__ __forceinline__ uint32_t pkbf(float a, float b) {
    __nv_bfloat162 t = __floats2bfloat162_rn(a, b);
    return *(uint32_t*)&t;
}
__device__ __forceinline__ void splitf(float v, __nv_bfloat16& h,
                                       __nv_bfloat16& l) {
    h = __float2bfloat16(v);
    l = __float2bfloat16(v - __bfloat162float(h));
}

// ---------------- cp.async helpers -----------------------------------------
__device__ __forceinline__ void cpa16(uint32_t dst, const void* src) {
    asm volatile("cp.async.cg.shared.global [%0], [%1], 16;"
                 :: "r"(dst), "l"(src));
}
#define CP_COMMIT() asm volatile("cp.async.commit_group;" ::: "memory")
#define CP_WAIT1() asm volatile("cp.async.wait_group 1;" ::: "memory")

// ---------------------------------------------------------------------------
// Split fp32 -> bf16 hi/lo. which: 0=x, 1..4=Wq..Wo
// ---------------------------------------------------------------------------
__global__ __launch_bounds__(256) void cvt_split(const float* __restrict__ src,
                                                 int which) {
    const int i = 4 * (blockIdx.x * blockDim.x + threadIdx.x);
    __nv_bfloat16 *h, *l;
    if (which == 0) { h = g_xh; l = g_xl; }
    else            { h = g_wh + (size_t)(which - 1) * NHID * NHID;
                      l = g_wl + (size_t)(which - 1) * NHID * NHID; }

    float4 v = *(const float4*)(src + i);
    __nv_bfloat16 h0, h1, h2, h3, l0, l1, l2, l3;
    splitf(v.x, h0, l0);
    splitf(v.y, h1, l1);
    splitf(v.z, h2, l2);
    splitf(v.w, h3, l3);
    *(__nv_bfloat162*)(h + i)     = __nv_bfloat162(h0, h1);
    *(__nv_bfloat162*)(h + i + 2) = __nv_bfloat162(h2, h3);
    *(__nv_bfloat162*)(l + i)     = __nv_bfloat162(l0, l1);
    *(__nv_bfloat162*)(l + i + 2) = __nv_bfloat162(l2, l3);
}

// ---------------------------------------------------------------------------
// HMMA GEMM, cp.async double-buffered. C = A*W^T + bias, split-bf16 3-pass.
// CTA 128x128, 8 warps (2x4). K-chunks of 32, 2 stages, stride-40 smem.
// PROJ=0: z=0/1/2 -> q/k (fp32, pre-rope) / v (split bf16 direct).
// PROJ=1: out projection from g_aoh/g_aol to Cout fp32.
// ---------------------------------------------------------------------------
#define KC2 32
#define NKC2 (NHID / KC2)   // 32
#define GSTR 40
#define GSTAGE (4 * 128 * GSTR)   // bf16 elems per stage

template <int PROJ>
__global__ __launch_bounds__(256) void gemm_mma(const float* __restrict__ b0p,
                                                const float* __restrict__ b1p,
                                                const float* __restrict__ b2p,
                                                float* __restrict__ Cout) {
    extern __shared__ __nv_bfloat16 sb[];

    const int tid = threadIdx.x;
    const int wid = tid >> 5;
    const int lane = tid & 31;
    const int wr = wid >> 2;
    const int wc = wid & 3;

    const int n0 = blockIdx.x * 128;
    const int m0 = blockIdx.y * 128;
    const int z = PROJ ? 3 : blockIdx.z;

    const __nv_bfloat16* Ah = PROJ ? g_aoh : g_xh;
    const __nv_bfloat16* Al = PROJ ? g_aol : g_xl;
    const __nv_bfloat16* Wh = g_wh + (size_t)z * NHID * NHID;
    const __nv_bfloat16* Wl = g_wl + (size_t)z * NHID * NHID;
    const float* bias = PROJ ? b0p : (z == 0 ? b0p : (z == 1 ? b1p : b2p));

    const __nv_bfloat16* gsrc[4] = {Ah + (size_t)m0 * NHID, Al + (size_t)m0 * NHID,
                                    Wh + (size_t)n0 * NHID, Wl + (size_t)n0 * NHID};

    float acc[4][4][4];
#pragma unroll
    for (int mt = 0; mt < 4; mt++)
#pragma unroll
        for (int nt = 0; nt < 4; nt++)
#pragma unroll
            for (int e = 0; e < 4; e++) acc[mt][nt][e] = 0.0f;

    const uint32_t uS = smem_u32(sb);

    auto load_chunk = [&](int c, int stage) {
        const int kc = c * KC2;
        const uint32_t sdst = uS + 2u * (uint32_t)(stage * GSTAGE);
#pragma unroll
        for (int t = 0; t < 4; t++) {
            const uint32_t db = sdst + 2u * (uint32_t)(t * 128 * GSTR);
            const __nv_bfloat16* src = gsrc[t];
#pragma unroll
            for (int i = 0; i < 2; i++) {
                const int idx = tid + 256 * i;
                const int row = idx >> 2;
                const int seg = idx & 3;
                cpa16(db + 2u * (uint32_t)(row * GSTR + seg * 8),
                      src + (size_t)row * NHID + kc + seg * 8);
            }
        }
    };

    const int a_row = lane & 15;
    const int a_koff = (lane >> 4) * 8;
    const int b_row = (lane & 7) + ((lane >> 4) & 1) * 8;
    const int b_koff = ((lane >> 3) & 1) * 8;

    load_chunk(0, 0);
    CP_COMMIT();
    load_chunk(1, 1);
    CP_COMMIT();

    for (int c = 0; c < NKC2; c++) {
        CP_WAIT1();
        __syncthreads();

        const uint32_t sstage = uS + 2u * (uint32_t)((c & 1) * GSTAGE);
        const uint32_t uAh = sstage;
        const uint32_t uAl = sstage + 2u * (128 * GSTR);
        const uint32_t uWh = sstage + 2u * (2 * 128 * GSTR);
        const uint32_t uWl = sstage + 2u * (3 * 128 * GSTR);

#pragma unroll
        for (int k16 = 0; k16 < 2; k16++) {
            const int kel = k16 * 16;
            uint32_t ah[4][4], al[4][4], bh[8], bl[8];
#pragma unroll
            for (int mt = 0; mt < 4; mt++) {
                const uint32_t off =
                    2u * ((64 * wr + 16 * mt + a_row) * GSTR + kel + a_koff);
                LDSM4(ah[mt][0], ah[mt][1], ah[mt][2], ah[mt][3], uAh + off);
                LDSM4(al[mt][0], al[mt][1], al[mt][2], al[mt][3], uAl + off);
            }
#pragma unroll
            for (int np = 0; np < 2; np++) {
                const uint32_t off =
                    2u * ((32 * wc + 16 * np + b_row) * GSTR + kel + b_koff);
                LDSM4(bh[4 * np], bh[4 * np + 1], bh[4 * np + 2], bh[4 * np + 3],
                      uWh + off);
                LDSM4(bl[4 * np], bl[4 * np + 1], bl[4 * np + 2], bl[4 * np + 3],
                      uWl + off);
            }
#pragma unroll
            for (int mt = 0; mt < 4; mt++)
#pragma unroll
                for (int nt = 0; nt < 4; nt++) {
                    const uint32_t* bt_h = &bh[4 * (nt >> 1) + 2 * (nt & 1)];
                    const uint32_t* bt_l = &bl[4 * (nt >> 1) + 2 * (nt & 1)];
                    mma_bf16(acc[mt][nt], ah[mt], bt_h);
                    mma_bf16(acc[mt][nt], ah[mt], bt_l);
                    mma_bf16(acc[mt][nt], al[mt], bt_h);
                }
        }
        __syncthreads();
        if (c + 2 < NKC2) load_chunk(c + 2, c & 1);
        CP_COMMIT();
    }

    // ---- epilogue ----
    const int mrow = (lane >> 2);
    const int ncol = (lane & 3) * 2;
#pragma unroll
    for (int mt = 0; mt < 4; mt++) {
#pragma unroll
        for (int half = 0; half < 2; half++) {
            const int m = m0 + 64 * wr + 16 * mt + mrow + 8 * half;
#pragma unroll
            for (int nt = 0; nt < 4; nt++) {
                const int n = n0 + 32 * wc + 8 * nt + ncol;
                float v0 = acc[mt][nt][2 * half] + bias[n];
                float v1 = acc[mt][nt][2 * half + 1] + bias[n + 1];
                if (PROJ) {
                    *(float2*)&Cout[(size_t)m * NHID + n] = make_float2(v0, v1);
                } else {
                    const int bb = m >> 11;
                    const int s = m & (NS - 1);
                    const int h = n >> 6;
                    const int d = n & (HDIM - 1);
                    const size_t o =
                        (((size_t)(bb * NHEADS + h) * NS + s) * HDIM + d);
                    if (z == 2) {   // V: store split bf16 directly
                        __nv_bfloat16 h0, h1, l0, l1;
                        splitf(v0, h0, l0);
                        splitf(v1, h1, l1);
                        *(__nv_bfloat162*)&g_vh[o] = __nv_bfloat162(h0, h1);
                        *(__nv_bfloat162*)&g_vl[o] = __nv_bfloat162(l0, l1);
                    } else {
                        float* dst = (z == 0) ? g_q : g_k;
                        *(float2*)&dst[o] = make_float2(v0, v1);
                    }
                }
            }
        }
    }
}

// ---------------------------------------------------------------------------
// RoPE: fp64 table; apply reads fp32 q/k, rotates, splits to bf16 hi/lo
// (q additionally scaled by 0.125 for attention).
// ---------------------------------------------------------------------------
__global__ void rope_table() {
    const int t = blockIdx.x * blockDim.x + threadIdx.x;   // 65536
    const int d = t & 31;
    const int s = t >> 5;
    const double inv = exp2(-(double)d * 0.41524101186092029);
    double sd, cd;
    sincos((double)s * inv, &sd, &cd);
    g_cos[t] = (float)cd;
    g_sin[t] = (float)sd;
}

__global__ __launch_bounds__(256) void rope_apply() {
    int t = blockIdx.x * blockDim.x + threadIdx.x;
    const int half = NB * NHEADS * NS * 8;
    const bool isq = (t < half);
    if (!isq) t -= half;
    const int dg = t & 7;
    const int s = (t >> 3) & (NS - 1);
    const int bh = t >> 14;

    const float4 c4 = *(const float4*)&g_cos[s * 32 + dg * 4];
    const float4 s4 = *(const float4*)&g_sin[s * 32 + dg * 4];

    const size_t off = ((size_t)bh * NS + s) * HDIM + dg * 4;
    const float* p = (isq ? g_q : g_k) + off;
    float4 x1 = *(const float4*)(p);
    float4 x2 = *(const float4*)(p + 32);
    float4 r1, r2;
    r1.x = x1.x * c4.x - x2.x * s4.x;  r2.x = x2.x * c4.x + x1.x * s4.x;
    r1.y = x1.y * c4.y - x2.y * s4.y;  r2.y = x2.y * c4.y + x1.y * s4.y;
    r1.z = x1.z * c4.z - x2.z * s4.z;  r2.z = x2.z * c4.z + x1.z * s4.z;
    r1.w = x1.w * c4.w - x2.w * s4.w;  r2.w = x2.w * c4.w + x1.w * s4.w;
    if (isq) {
        r1.x *= 0.125f; r1.y *= 0.125f; r1.z *= 0.125f; r1.w *= 0.125f;
        r2.x *= 0.125f; r2.y *= 0.125f; r2.z *= 0.125f; r2.w *= 0.125f;
    }
    __nv_bfloat16* dh = (isq ? g_qh : g_kh) + off;
    __nv_bfloat16* dl = (isq ? g_ql : g_kl) + off;
    __nv_bfloat16 h0, h1, h2, h3, l0, l1, l2, l3;
    splitf(r1.x, h0, l0); splitf(r1.y, h1, l1);
    splitf(r1.z, h2, l2); splitf(r1.w, h3, l3);
    *(__nv_bfloat162*)(dh)     = __nv_bfloat162(h0, h1);
    *(__nv_bfloat162*)(dh + 2) = __nv_bfloat162(h2, h3);
    *(__nv_bfloat162*)(dl)     = __nv_bfloat162(l0, l1);
    *(__nv_bfloat162*)(dl + 2) = __nv_bfloat162(l2, l3);
    splitf(r2.x, h0, l0); splitf(r2.y, h1, l1);
    splitf(r2.z, h2, l2); splitf(r2.w, h3, l3);
    *(__nv_bfloat162*)(dh + 32) = __nv_bfloat162(h0, h1);
    *(__nv_bfloat162*)(dh + 34) = __nv_bfloat162(h2, h3);
    *(__nv_bfloat162*)(dl + 32) = __nv_bfloat162(l0, l1);
    *(__nv_bfloat162*)(dl + 34) = __nv_bfloat162(l2, l3);
}

// ---------------------------------------------------------------------------
// Flash attention via HMMA, cp.async double-buffered K/V.
// CTA = (b, h, 128-row q tile); 8 warps x 16 q-rows; K/V tiles of 64.
// All operands pre-split bf16 in global. Output written pre-split.
// ---------------------------------------------------------------------------
#define BQ 128
#define BK 64
#define KSTR 72
#define KVSTAGE (4 * 64 * KSTR)   // bf16 elems per stage (kh,kl,vh,vl)

__global__ __launch_bounds__(256, 2) void attn_mma() {
    extern __shared__ __nv_bfloat16 sa_[];
    __nv_bfloat16* sQh = sa_;                    // 128*72
    __nv_bfloat16* sQl = sa_ + 128 * KSTR;
    __nv_bfloat16* sKV = sa_ + 2 * 128 * KSTR;   // 2 stages

    const int qt = (int)(gridDim.x - 1) - (int)blockIdx.x;   // big tiles first
    const int h = blockIdx.y;
    const int b = blockIdx.z;
    const int tid = threadIdx.x;
    const int wid = tid >> 5;
    const int lane = tid & 31;

    const size_t bhoff = (size_t)(b * NHEADS + h) * NS * HDIM;
    const __nv_bfloat16* kvsrc[4] = {g_kh + bhoff, g_kl + bhoff,
                                     g_vh + bhoff, g_vl + bhoff};

    const uint32_t uQh = smem_u32(sQh);
    const uint32_t uQl = smem_u32(sQl);
    const uint32_t uKV = smem_u32(sKV);

    auto load_tile = [&](int kt, int stage) {
        const uint32_t sdst = uKV + 2u * (uint32_t)(stage * KVSTAGE);
        const size_t gb = (size_t)kt * BK * HDIM;
#pragma unroll
        for (int t = 0; t < 4; t++) {
            const __nv_bfloat16* src = kvsrc[t] + gb;
            const uint32_t db = sdst + 2u * (uint32_t)(t * 64 * KSTR);
#pragma unroll
            for (int i = 0; i < 2; i++) {
                const int idx = tid + 256 * i;
                const int row = idx >> 3;
                const int seg = idx & 7;
                cpa16(db + 2u * (uint32_t)(row * KSTR + seg * 8),
                      src + row * HDIM + seg * 8);
            }
        }
    };

    // ---- load Q tile (pre-scaled, pre-split) ----
    {
        const int row = tid >> 1;
        const int c0 = (tid & 1) * 32;
        const __nv_bfloat16* sh = g_qh + bhoff + ((size_t)qt * BQ + row) * HDIM + c0;
        const __nv_bfloat16* sl = g_ql + bhoff + ((size_t)qt * BQ + row) * HDIM + c0;
        __nv_bfloat16* dh = sQh + row * KSTR + c0;
        __nv_bfloat16* dl = sQl + row * KSTR + c0;
#pragma unroll
        for (int j = 0; j < 4; j++) {
            *(uint4*)(dh + 8 * j) = *(const uint4*)(sh + 8 * j);
            *(uint4*)(dl + 8 * j) = *(const uint4*)(sl + 8 * j);
        }
    }

    const int a_row = lane & 15;
    const int a_koff = (lane >> 4) * 8;
    const int b_row = (lane & 7) + ((lane >> 4) & 1) * 8;
    const int b_koff = ((lane >> 3) & 1) * 8;
    const int v_kr = (lane & 7) + 8 * ((lane >> 3) & 1);
    const int v_nc = 8 * (lane >> 4);

    float o[8][4];
#pragma unroll
    for (int j = 0; j < 8; j++)
#pragma unroll
        for (int e = 0; e < 4; e++) o[j][e] = 0.0f;
    float mi0 = -1e30f, mi1 = -1e30f, li0 = 0.0f, li1 = 0.0f;

    const int qrow0 = qt * BQ + wid * 16 + (lane >> 2);
    const int qrow1 = qrow0 + 8;
    const int kcbase = 2 * (lane & 3);

    const int ktmax = 2 * qt + 1;   // >= 1 always
    load_tile(0, 0);
    CP_COMMIT();
    load_tile(1, 1);
    CP_COMMIT();

    for (int kt = 0; kt <= ktmax; kt++) {
        CP_WAIT1();
        __syncthreads();

        const uint32_t sstage = uKV + 2u * (uint32_t)((kt & 1) * KVSTAGE);
        const uint32_t uKh = sstage;
        const uint32_t uKl = sstage + 2u * (64 * KSTR);
        const uint32_t uVh = sstage + 2u * (2 * 64 * KSTR);
        const uint32_t uVl = sstage + 2u * (3 * 64 * KSTR);

        // ---- S = Q @ K^T ----
        float s[8][4];
#pragma unroll
        for (int j = 0; j < 8; j++)
#pragma unroll
            for (int e = 0; e < 4; e++) s[j][e] = 0.0f;

#pragma unroll
        for (int k16 = 0; k16 < 4; k16++) {
            const int kel = 16 * k16;
            uint32_t qh[4], ql[4], kh[4][4], kl[4][4];
            {
                const uint32_t off =
                    2u * ((wid * 16 + a_row) * KSTR + kel + a_koff);
                LDSM4(qh[0], qh[1], qh[2], qh[3], uQh + off);
                LDSM4(ql[0], ql[1], ql[2], ql[3], uQl + off);
            }
#pragma unroll
            for (int ng = 0; ng < 4; ng++) {
                const uint32_t off =
                    2u * ((16 * ng + b_row) * KSTR + kel + b_koff);
                LDSM4(kh[ng][0], kh[ng][1], kh[ng][2], kh[ng][3], uKh + off);
                LDSM4(kl[ng][0], kl[ng][1], kl[ng][2], kl[ng][3], uKl + off);
            }
#pragma unroll
            for (int j = 0; j < 8; j++) {
                const uint32_t* bh = &kh[j >> 1][2 * (j & 1)];
                const uint32_t* bl = &kl[j >> 1][2 * (j & 1)];
                mma_bf16(s[j], qh, bh);
                mma_bf16(s[j], qh, bl);
                mma_bf16(s[j], ql, bh);
            }
        }

        // ---- causal mask ----
        if (kt * BK + BK - 1 > qrow0) {
#pragma unroll
            for (int j = 0; j < 8; j++) {
                const int kc = kt * BK + 8 * j + kcbase;
                if (kc > qrow0) s[j][0] = -1e30f;
                if (kc + 1 > qrow0) s[j][1] = -1e30f;
            }
        }
        if (kt * BK + BK - 1 > qrow1) {
#pragma unroll
            for (int j = 0; j < 8; j++) {
                const int kc = kt * BK + 8 * j + kcbase;
                if (kc > qrow1) s[j][2] = -1e30f;
                if (kc + 1 > qrow1) s[j][3] = -1e30f;
            }
        }

        // ---- online softmax ----
        float mx0 = s[0][0], mx1 = s[0][2];
#pragma unroll
        for (int j = 0; j < 8; j++) {
            mx0 = fmaxf(mx0, fmaxf(s[j][0], s[j][1]));
            mx1 = fmaxf(mx1, fmaxf(s[j][2], s[j][3]));
        }
        mx0 = fmaxf(mx0, __shfl_xor_sync(0xffffffffu, mx0, 1));
        mx0 = fmaxf(mx0, __shfl_xor_sync(0xffffffffu, mx0, 2));
        mx1 = fmaxf(mx1, __shfl_xor_sync(0xffffffffu, mx1, 1));
        mx1 = fmaxf(mx1, __shfl_xor_sync(0xffffffffu, mx1, 2));

        const float mn0 = fmaxf(mi0, mx0);
        const float mn1 = fmaxf(mi1, mx1);
        const float cr0 = __expf(mi0 - mn0);
        const float cr1 = __expf(mi1 - mn1);

        float rs0 = 0.0f, rs1 = 0.0f;
#pragma unroll
        for (int j = 0; j < 8; j++) {
            s[j][0] = __expf(s[j][0] - mn0);
            s[j][1] = __expf(s[j][1] - mn0);
            s[j][2] = __expf(s[j][2] - mn1);
            s[j][3] = __expf(s[j][3] - mn1);
            rs0 += s[j][0] + s[j][1];
            rs1 += s[j][2] + s[j][3];
        }
        rs0 += __shfl_xor_sync(0xffffffffu, rs0, 1);
        rs0 += __shfl_xor_sync(0xffffffffu, rs0, 2);
        rs1 += __shfl_xor_sync(0xffffffffu, rs1, 1);
        rs1 += __shfl_xor_sync(0xffffffffu, rs1, 2);
        li0 = li0 * cr0 + rs0;
        li1 = li1 * cr1 + rs1;
        mi0 = mn0;
        mi1 = mn1;

#pragma unroll
        for (int j = 0; j < 8; j++) {
            o[j][0] *= cr0;
            o[j][1] *= cr0;
            o[j][2] *= cr1;
            o[j][3] *= cr1;
        }

        // ---- O += P @ V ----
#pragma unroll
        for (int t = 0; t < 4; t++) {
            uint32_t ph[4], pl[4];
            {
                const float* p0 = s[2 * t];
                const float* p1 = s[2 * t + 1];
                __nv_bfloat16 hh, ll;
                float hf[8], lf[8];
#pragma unroll
                for (int e = 0; e < 4; e++) {
                    splitf(p0[e], hh, ll);
                    hf[e] = __bfloat162float(hh);
                    lf[e] = __bfloat162float(ll);
                    splitf(p1[e], hh, ll);
                    hf[4 + e] = __bfloat162float(hh);
                    lf[4 + e] = __bfloat162float(ll);
                }
                ph[0] = pkbf(hf[0], hf[1]);
                ph[1] = pkbf(hf[2], hf[3]);
                ph[2] = pkbf(hf[4], hf[5]);
                ph[3] = pkbf(hf[6], hf[7]);
                pl[0] = pkbf(lf[0], lf[1]);
                pl[1] = pkbf(lf[2], lf[3]);
                pl[2] = pkbf(lf[4], lf[5]);
                pl[3] = pkbf(lf[6], lf[7]);
            }
            const int kel = 16 * t;
            uint32_t vh[4][4], vl[4][4];
#pragma unroll
            for (int ng = 0; ng < 4; ng++) {
                const uint32_t off =
                    2u * ((kel + v_kr) * KSTR + 16 * ng + v_nc);
                LDSM4T(vh[ng][0], vh[ng][1], vh[ng][2], vh[ng][3], uVh + off);
                LDSM4T(vl[ng][0], vl[ng][1], vl[ng][2], vl[ng][3], uVl + off);
            }
#pragma unroll
            for (int j = 0; j < 8; j++) {
                const uint32_t* bvh = &vh[j >> 1][2 * (j & 1)];
                const uint32_t* bvl = &vl[j >> 1][2 * (j & 1)];
                mma_bf16(o[j], ph, bvh);
                mma_bf16(o[j], ph, bvl);
                mma_bf16(o[j], pl, bvh);
            }
        }

        __syncthreads();
        if (kt + 2 <= ktmax) load_tile(kt + 2, kt & 1);
        CP_COMMIT();
    }

    // ---- normalize + store SPLIT to g_aoh/g_aol [b, s, h*64+d] ----
    const float inv0 = 1.0f / li0;
    const float inv1 = 1.0f / li1;
    const size_t o0 = ((size_t)b * NS + qrow0) * NHID + h * HDIM;
    const size_t o1 = ((size_t)b * NS + qrow1) * NHID + h * HDIM;
#pragma unroll
    for (int j = 0; j < 8; j++) {
        const int d = 8 * j + kcbase;
        __nv_bfloat16 h0, h1, l0, l1;
        splitf(o[j][0] * inv0, h0, l0);
        splitf(o[j][1] * inv0, h1, l1);
        *(__nv_bfloat162*)&g_aoh[o0 + d] = __nv_bfloat162(h0, h1);
        *(__nv_bfloat162*)&g_aol[o0 + d] = __nv_bfloat162(l0, l1);
        splitf(o[j][2] * inv1, h0, l0);
        splitf(o[j][3] * inv1, h1, l1);
        *(__nv_bfloat162*)&g_aoh[o1 + d] = __nv_bfloat162(h0, h1);
        *(__nv_bfloat162*)&g_aol[o1 + d] = __nv_bfloat162(l0, l1);
    }
}

// ---------------------------------------------------------------------------
extern "C" void kernel_launch(void* const* d_in, const int* in_sizes, int n_in,
                              void* d_out, int out_size) {
    const float* x  = (const float*)d_in[0];
    const float* Wq = (const float*)d_in[1];
    const float* bq = (const float*)d_in[2];
    const float* Wk = (const float*)d_in[3];
    const float* bk = (const float*)d_in[4];
    const float* Wv = (const float*)d_in[5];
    const float* bv = (const float*)d_in[6];
    const float* Wo = (const float*)d_in[7];
    const float* bo = (const float*)d_in[8];
    float* out = (float*)d_out;

    const int GEMM_SMEM = 2 * GSTAGE * 2;                       // 81920 B
    const int ATTN_SMEM = (2 * 128 * KSTR + 2 * KVSTAGE) * 2;   // 110592 B
    cudaFuncSetAttribute(gemm_mma<0>, cudaFuncAttributeMaxDynamicSharedMemorySize,
                         GEMM_SMEM);
    cudaFuncSetAttribute(gemm_mma<1>, cudaFuncAttributeMaxDynamicSharedMemorySize,
                         GEMM_SMEM);
    cudaFuncSetAttribute(attn_mma, cudaFuncAttributeMaxDynamicSharedMemorySize,
                         ATTN_SMEM);

    rope_table<<<NS * 32 / 256, 256>>>();

    cvt_split<<<MM * NHID / 1024, 256>>>(x, 0);
    cvt_split<<<NHID * NHID / 1024, 256>>>(Wq, 1);
    cvt_split<<<NHID * NHID / 1024, 256>>>(Wk, 2);
    cvt_split<<<NHID * NHID / 1024, 256>>>(Wv, 3);
    cvt_split<<<NHID * NHID / 1024, 256>>>(Wo, 4);

    gemm_mma<0><<<dim3(NHID / 128, MM / 128, 3), 256, GEMM_SMEM>>>(bq, bk, bv,
                                                                   nullptr);

    rope_apply<<<2 * NB * NHEADS * NS * 8 / 256, 256>>>();

    attn_mma<<<dim3(NS / BQ, NHEADS, NB), 256, ATTN_SMEM>>>();

    gemm_mma<1><<<dim3(NHID / 128, MM / 128), 256, GEMM_SMEM>>>(bo, nullptr,
                                                                nullptr, out);
}